// round 1
// baseline (speedup 1.0000x reference)
#include <cuda_runtime.h>
#include <math.h>

// Problem constants
#define B_  4
#define T_  1024
#define D_  1024
#define H_  16
#define HD  64
#define BH  (B_*H_)     // 64
#define M_  (B_*T_)     // 4096

// Scratch (static device globals — no allocation)
__device__ float g_q[(size_t)BH*T_*HD];       // [bh][t][d]
__device__ float g_k[(size_t)BH*T_*HD];
__device__ float g_v[(size_t)BH*T_*HD];
__device__ float g_ctx[(size_t)M_*D_];        // [b*T+t][D]
__device__ float g_gate[BH*T_];               // [bh][t]
__device__ float g_pb[H_*2048];               // [h][rel+1023]
__device__ float g_scores[(size_t)BH*T_*T_];  // [bh][q][k]  (256 MB)

// ---------------------------------------------------------------------------
// Position-bias LUT: bucket depends only on rel = k - q in [-1023, 1023]
// ---------------------------------------------------------------------------
__global__ void pb_kernel(const float* __restrict__ rel_embed)
{
    int d = blockIdx.x * blockDim.x + threadIdx.x;
    if (d >= 2047) return;
    int rel = d - 1023;
    int rb  = (rel > 0) ? 160 : 0;
    int rp  = rel < 0 ? -rel : rel;
    int bucket;
    if (rp < 80) {
        bucket = rb + rp;
    } else {
        float t = logf((float)rp / 80.0f) / logf(10.0f);
        t = t * 80.0f;
        float v = 80.0f + t;
        int bi = (int)v;                 // truncation matches .astype(int32)
        bucket = rb + (bi < 159 ? bi : 159);
    }
    #pragma unroll
    for (int h = 0; h < H_; h++)
        g_pb[h*2048 + d] = rel_embed[bucket*H_ + h];
}

// ---------------------------------------------------------------------------
// Gate: per (b,h,t) scalar.  proj = x(64) @ gru_w^T(8,64) + gru_b,
// reshape (2,4).sum -> sigmoid -> ga*(gb*gc[h]-1)+2
// ---------------------------------------------------------------------------
__global__ void gate_kernel(const float* __restrict__ hs,
                            const float* __restrict__ gw,
                            const float* __restrict__ gb,
                            const float* __restrict__ gc)
{
    int idx = blockIdx.x * blockDim.x + threadIdx.x;
    if (idx >= BH*T_) return;
    int t  = idx & (T_-1);
    int bh = idx >> 10;
    int h  = bh & (H_-1);
    int b  = bh >> 4;

    const float4* x = (const float4*)(hs + ((size_t)(b*T_+t))*D_ + h*HD);
    float p[8];
    #pragma unroll
    for (int e = 0; e < 8; e++) p[e] = 0.f;
    #pragma unroll
    for (int i = 0; i < 16; i++) {
        float4 xv = x[i];
        #pragma unroll
        for (int e = 0; e < 8; e++) {
            const float* w = gw + e*HD + i*4;
            p[e] += xv.x*w[0] + xv.y*w[1] + xv.z*w[2] + xv.w*w[3];
        }
    }
    float pa = p[0]+p[1]+p[2]+p[3] + gb[0]+gb[1]+gb[2]+gb[3];
    float pbv= p[4]+p[5]+p[6]+p[7] + gb[4]+gb[5]+gb[6]+gb[7];
    float ga  = 1.f/(1.f + expf(-pa));
    float gbs = 1.f/(1.f + expf(-pbv));
    g_gate[idx] = ga * (gbs * gc[h] - 1.f) + 2.f;
}

// ---------------------------------------------------------------------------
// Projection GEMM: C[M,N] = A[M,K] @ W[N,K]^T, +bias, *scale.
// remap!=0 : write in [bh][t][d] layout (for q/k/v); else row-major [m][n].
// 64x64 tile, BK=16, 256 threads, 4x4 micro-tile.
// ---------------------------------------------------------------------------
__global__ void proj_kernel(const float* __restrict__ A,
                            const float* __restrict__ W,
                            const float* __restrict__ bias,
                            float* __restrict__ out,
                            float scale, int remap)
{
    __shared__ float As[16][65];
    __shared__ float Bs[16][65];

    const int K = D_;
    const int n0 = blockIdx.x * 64;
    const int m0 = blockIdx.y * 64;
    const int tid = threadIdx.x;
    const int tx = tid & 15, ty = tid >> 4;
    const int lr = tid >> 2;        // 0..63 (tile row for loads)
    const int lc = (tid & 3) * 4;   // 0,4,8,12 (k-offset for loads)

    float acc[4][4];
    #pragma unroll
    for (int i = 0; i < 4; i++)
        #pragma unroll
        for (int j = 0; j < 4; j++) acc[i][j] = 0.f;

    for (int kt = 0; kt < K; kt += 16) {
        float4 av = *(const float4*)(A + (size_t)(m0 + lr)*K + kt + lc);
        float4 wv = *(const float4*)(W + (size_t)(n0 + lr)*K + kt + lc);
        As[lc+0][lr] = av.x; As[lc+1][lr] = av.y; As[lc+2][lr] = av.z; As[lc+3][lr] = av.w;
        Bs[lc+0][lr] = wv.x; Bs[lc+1][lr] = wv.y; Bs[lc+2][lr] = wv.z; Bs[lc+3][lr] = wv.w;
        __syncthreads();
        #pragma unroll
        for (int kk = 0; kk < 16; kk++) {
            float a[4], b[4];
            #pragma unroll
            for (int i = 0; i < 4; i++) a[i] = As[kk][ty*4+i];
            #pragma unroll
            for (int j = 0; j < 4; j++) b[j] = Bs[kk][tx*4+j];
            #pragma unroll
            for (int i = 0; i < 4; i++)
                #pragma unroll
                for (int j = 0; j < 4; j++) acc[i][j] += a[i]*b[j];
        }
        __syncthreads();
    }

    #pragma unroll
    for (int i = 0; i < 4; i++) {
        int m = m0 + ty*4 + i;
        #pragma unroll
        for (int j = 0; j < 4; j++) {
            int n = n0 + tx*4 + j;
            float v = (acc[i][j] + bias[n]) * scale;
            if (remap) {
                int b = m >> 10, t = m & 1023;
                int h = n >> 6,  d = n & 63;
                out[(((size_t)(b*H_ + h)*T_ + t))*HD + d] = v;
            } else {
                out[(size_t)m*D_ + n] = v;
            }
        }
    }
}

// ---------------------------------------------------------------------------
// Scores: S[bh][q][k] = Q.K + gate[bh][q] * pb[h][k-q+1023]
// grid (kt, qt, bh); 64x64 tile over full d=64.
// ---------------------------------------------------------------------------
__global__ void scores_kernel()
{
    __shared__ float Qs[64][65];   // [d][q]
    __shared__ float Ks[64][65];   // [d][k]

    const int kt = blockIdx.x, qt = blockIdx.y, bh = blockIdx.z;
    const int h  = bh & 15;
    const int tid = threadIdx.x;
    const int tx = tid & 15, ty = tid >> 4;

    const float* Q = g_q + ((size_t)bh*T_ + qt*64)*HD;
    const float* K = g_k + ((size_t)bh*T_ + kt*64)*HD;

    #pragma unroll
    for (int f = tid; f < 1024; f += 256) {
        int r = f >> 4, c = (f & 15) * 4;
        float4 qv = *(const float4*)(Q + r*HD + c);
        float4 kv = *(const float4*)(K + r*HD + c);
        Qs[c+0][r]=qv.x; Qs[c+1][r]=qv.y; Qs[c+2][r]=qv.z; Qs[c+3][r]=qv.w;
        Ks[c+0][r]=kv.x; Ks[c+1][r]=kv.y; Ks[c+2][r]=kv.z; Ks[c+3][r]=kv.w;
    }
    __syncthreads();

    float acc[4][4];
    #pragma unroll
    for (int i = 0; i < 4; i++)
        #pragma unroll
        for (int j = 0; j < 4; j++) acc[i][j] = 0.f;

    #pragma unroll
    for (int d = 0; d < 64; d++) {
        float a[4], b[4];
        #pragma unroll
        for (int i = 0; i < 4; i++) a[i] = Qs[d][ty*4+i];
        #pragma unroll
        for (int j = 0; j < 4; j++) b[j] = Ks[d][tx*4+j];
        #pragma unroll
        for (int i = 0; i < 4; i++)
            #pragma unroll
            for (int j = 0; j < 4; j++) acc[i][j] += a[i]*b[j];
    }

    float gt[4];
    #pragma unroll
    for (int i = 0; i < 4; i++) gt[i] = g_gate[bh*T_ + qt*64 + ty*4 + i];

    #pragma unroll
    for (int i = 0; i < 4; i++) {
        int q = qt*64 + ty*4 + i;
        float* row = g_scores + ((size_t)bh*T_ + q)*T_;
        #pragma unroll
        for (int j = 0; j < 4; j++) {
            int k = kt*64 + tx*4 + j;
            row[k] = acc[i][j] + gt[i] * g_pb[h*2048 + (k - q + 1023)];
        }
    }
}

// ---------------------------------------------------------------------------
// Row softmax over 1024, in place. One block per row, 256 thr x float4.
// ---------------------------------------------------------------------------
__global__ void softmax_kernel()
{
    __shared__ float smax[8], ssum[8];
    float* p = g_scores + (size_t)blockIdx.x * T_;
    int tid = threadIdx.x;

    float4 v = ((const float4*)p)[tid];
    float m = fmaxf(fmaxf(v.x, v.y), fmaxf(v.z, v.w));
    #pragma unroll
    for (int o = 16; o > 0; o >>= 1) m = fmaxf(m, __shfl_xor_sync(0xffffffffu, m, o));
    if ((tid & 31) == 0) smax[tid >> 5] = m;
    __syncthreads();
    float mt = smax[0];
    #pragma unroll
    for (int w = 1; w < 8; w++) mt = fmaxf(mt, smax[w]);

    float e0 = expf(v.x - mt), e1 = expf(v.y - mt);
    float e2 = expf(v.z - mt), e3 = expf(v.w - mt);
    float s = e0 + e1 + e2 + e3;
    #pragma unroll
    for (int o = 16; o > 0; o >>= 1) s += __shfl_xor_sync(0xffffffffu, s, o);
    if ((tid & 31) == 0) ssum[tid >> 5] = s;
    __syncthreads();
    float st = 0.f;
    #pragma unroll
    for (int w = 0; w < 8; w++) st += ssum[w];
    float inv = 1.f / st;

    float4 o4 = make_float4(e0*inv, e1*inv, e2*inv, e3*inv);
    ((float4*)p)[tid] = o4;
}

// ---------------------------------------------------------------------------
// PV: O[bh][q][d] = P[bh][q][:] @ V[bh][:][d]; writes into ctx [b,t,D] layout.
// grid (qt, bh). 64(q) x 64(d), BK=64.
// ---------------------------------------------------------------------------
__global__ void av_kernel()
{
    __shared__ float Ps[64][68];   // [q][k]
    __shared__ float Vs[64][68];   // [k][d]

    const int qt = blockIdx.x, bh = blockIdx.y;
    const int b = bh >> 4, h = bh & 15;
    const int tid = threadIdx.x;
    const int tx = tid & 15, ty = tid >> 4;

    float acc[4][4];
    #pragma unroll
    for (int i = 0; i < 4; i++)
        #pragma unroll
        for (int j = 0; j < 4; j++) acc[i][j] = 0.f;

    for (int kt = 0; kt < 16; kt++) {
        const float* P = g_scores + ((size_t)bh*T_ + qt*64)*T_ + kt*64;
        const float* V = g_v + ((size_t)bh*T_ + kt*64)*HD;
        #pragma unroll
        for (int f = tid; f < 1024; f += 256) {
            int r = f >> 4, c = (f & 15) * 4;
            *(float4*)&Ps[r][c] = *(const float4*)(P + (size_t)r*T_ + c);
            *(float4*)&Vs[r][c] = *(const float4*)(V + r*HD + c);
        }
        __syncthreads();
        #pragma unroll
        for (int kk = 0; kk < 64; kk++) {
            float a[4], bb[4];
            #pragma unroll
            for (int i = 0; i < 4; i++) a[i] = Ps[ty*4+i][kk];
            #pragma unroll
            for (int j = 0; j < 4; j++) bb[j] = Vs[kk][tx*4+j];
            #pragma unroll
            for (int i = 0; i < 4; i++)
                #pragma unroll
                for (int j = 0; j < 4; j++) acc[i][j] += a[i]*bb[j];
        }
        __syncthreads();
    }

    #pragma unroll
    for (int i = 0; i < 4; i++) {
        int t = qt*64 + ty*4 + i;
        #pragma unroll
        for (int j = 0; j < 4; j++) {
            int d = tx*4 + j;
            g_ctx[((size_t)(b*T_ + t))*D_ + h*HD + d] = acc[i][j];
        }
    }
}

// ---------------------------------------------------------------------------
extern "C" void kernel_launch(void* const* d_in, const int* in_sizes, int n_in,
                              void* d_out, int out_size)
{
    const float* hs    = (const float*)d_in[0];
    const float* q_w   = (const float*)d_in[1];
    const float* q_b   = (const float*)d_in[2];
    const float* k_w   = (const float*)d_in[3];
    const float* k_b   = (const float*)d_in[4];
    const float* v_w   = (const float*)d_in[5];
    const float* v_b   = (const float*)d_in[6];
    const float* out_w = (const float*)d_in[7];
    const float* out_b = (const float*)d_in[8];
    const float* rel   = (const float*)d_in[9];
    const float* gc    = (const float*)d_in[10];
    const float* gw    = (const float*)d_in[11];
    const float* gb    = (const float*)d_in[12];

    float *pq, *pk, *pv, *pctx;
    cudaGetSymbolAddress((void**)&pq,  g_q);
    cudaGetSymbolAddress((void**)&pk,  g_k);
    cudaGetSymbolAddress((void**)&pv,  g_v);
    cudaGetSymbolAddress((void**)&pctx, g_ctx);

    pb_kernel<<<8, 256>>>(rel);
    gate_kernel<<<(BH*T_)/256, 256>>>(hs, gw, gb, gc);

    const float scaling = 0.125f;   // hd^-0.5, hd=64
    proj_kernel<<<dim3(16, 64), 256>>>(hs, q_w, q_b, pq, scaling, 1);
    proj_kernel<<<dim3(16, 64), 256>>>(hs, k_w, k_b, pk, 1.0f, 1);
    proj_kernel<<<dim3(16, 64), 256>>>(hs, v_w, v_b, pv, 1.0f, 1);

    scores_kernel<<<dim3(16, 16, BH), 256>>>();
    softmax_kernel<<<BH*T_, 256>>>();
    av_kernel<<<dim3(16, BH), 256>>>();

    proj_kernel<<<dim3(16, 64), 256>>>(pctx, out_w, out_b, (float*)d_out, 1.0f, 0);
}

// round 3
// speedup vs baseline: 1.7771x; 1.7771x over previous
#include <cuda_runtime.h>
#include <cuda_bf16.h>
#include <math.h>
#include <stdint.h>

// Problem constants
#define B_  4
#define T_  1024
#define D_  1024
#define H_  16
#define HD  64
#define BH  (B_*H_)     // 64
#define M_  (B_*T_)     // 4096

// Scratch (static device globals — no allocation)
__device__ float g_q[(size_t)BH*T_*HD];       // [bh][t][d]
__device__ float g_k[(size_t)BH*T_*HD];
__device__ float g_v[(size_t)BH*T_*HD];
__device__ float g_ctx[(size_t)M_*D_];        // [b*T+t][D]
__device__ float g_gate[BH*T_];               // [bh][t]
__device__ float g_pb[H_*2048];               // [h][rel+1023]
__device__ float g_scores[(size_t)BH*T_*T_];  // [bh][q][k]  (256 MB)

// bf16 split buffers
__device__ __nv_bfloat16 g_a_hi[(size_t)M_*D_];   // activations hi (hs, later ctx)
__device__ __nv_bfloat16 g_a_lo[(size_t)M_*D_];
__device__ __nv_bfloat16 g_w_hi[(size_t)4*D_*D_]; // 4 weight matrices hi
__device__ __nv_bfloat16 g_w_lo[(size_t)4*D_*D_];

// ---------------------------------------------------------------------------
// PTX helpers (mma.sync / ldmatrix / cp.async — all valid on base sm_100)
// ---------------------------------------------------------------------------
__device__ __forceinline__ uint32_t smem_u32(const void* p) {
    uint32_t a;
    asm("{ .reg .u64 t; cvta.to.shared.u64 t, %1; cvt.u32.u64 %0, t; }" : "=r"(a) : "l"(p));
    return a;
}
__device__ __forceinline__ void ldmx4(uint32_t* r, uint32_t addr) {
    asm volatile("ldmatrix.sync.aligned.m8n8.x4.shared.b16 {%0,%1,%2,%3}, [%4];"
        : "=r"(r[0]), "=r"(r[1]), "=r"(r[2]), "=r"(r[3]) : "r"(addr));
}
__device__ __forceinline__ void mma16816(float* c, const uint32_t* a, const uint32_t* b) {
    asm volatile("mma.sync.aligned.m16n8k16.row.col.f32.bf16.bf16.f32 "
        "{%0,%1,%2,%3}, {%4,%5,%6,%7}, {%8,%9}, {%0,%1,%2,%3};"
        : "+f"(c[0]), "+f"(c[1]), "+f"(c[2]), "+f"(c[3])
        : "r"(a[0]), "r"(a[1]), "r"(a[2]), "r"(a[3]), "r"(b[0]), "r"(b[1]));
}
__device__ __forceinline__ void cpasync16(uint32_t dst, const void* src) {
    asm volatile("cp.async.cg.shared.global [%0], [%1], 16;" :: "r"(dst), "l"(src));
}
#define CP_COMMIT()  asm volatile("cp.async.commit_group;" ::: "memory")
#define CP_WAIT(n)   asm volatile("cp.async.wait_group %0;" :: "n"(n) : "memory")

// ---------------------------------------------------------------------------
// Split fp32 -> bf16 hi/lo.  n4 = elements/4.
// ---------------------------------------------------------------------------
__global__ void split_kernel(const float* __restrict__ x,
                             __nv_bfloat16* __restrict__ hi,
                             __nv_bfloat16* __restrict__ lo, int n4)
{
    int i = blockIdx.x * blockDim.x + threadIdx.x;
    if (i >= n4) return;
    float4 v = ((const float4*)x)[i];
    __nv_bfloat16 h0 = __float2bfloat16_rn(v.x);
    __nv_bfloat16 h1 = __float2bfloat16_rn(v.y);
    __nv_bfloat16 h2 = __float2bfloat16_rn(v.z);
    __nv_bfloat16 h3 = __float2bfloat16_rn(v.w);
    __nv_bfloat16 l0 = __float2bfloat16_rn(v.x - __bfloat162float(h0));
    __nv_bfloat16 l1 = __float2bfloat16_rn(v.y - __bfloat162float(h1));
    __nv_bfloat16 l2 = __float2bfloat16_rn(v.z - __bfloat162float(h2));
    __nv_bfloat16 l3 = __float2bfloat16_rn(v.w - __bfloat162float(h3));
    __nv_bfloat162* hp = (__nv_bfloat162*)hi;
    __nv_bfloat162* lp = (__nv_bfloat162*)lo;
    hp[2*i+0] = __nv_bfloat162(h0, h1);
    hp[2*i+1] = __nv_bfloat162(h2, h3);
    lp[2*i+0] = __nv_bfloat162(l0, l1);
    lp[2*i+1] = __nv_bfloat162(l2, l3);
}

// ---------------------------------------------------------------------------
// mma.sync projection GEMM: C[4096,1024] = A @ W^T (bf16 hi/lo, fp32 accum)
// CTA 128x128, BK=32, 8 warps (2x4), warp tile 64x32, cp.async double buffer.
// ---------------------------------------------------------------------------
#define SST    40                 // smem row stride in bf16 (32 data + 8 pad)
#define MAT_B  (128*SST*2)        // bytes per matrix tile  = 10240
#define STG_B  (4*MAT_B)          // Ah, Al, Bh, Bl         = 40960
#define SMEMT  (2*STG_B)          // double buffered        = 81920

__global__ __launch_bounds__(256, 1)
void proj_mma_kernel(const __nv_bfloat16* __restrict__ Ahi,
                     const __nv_bfloat16* __restrict__ Alo,
                     const __nv_bfloat16* __restrict__ Whi,
                     const __nv_bfloat16* __restrict__ Wlo,
                     const float* __restrict__ bias,
                     float* __restrict__ out,
                     float scale, int remap)
{
    extern __shared__ char sm[];
    const uint32_t sb = smem_u32(sm);
    const int tid = threadIdx.x;
    const int lane = tid & 31, wid = tid >> 5;
    const int m0 = blockIdx.y * 128, n0 = blockIdx.x * 128;
    const int wm = (wid >> 2) * 64, wn = (wid & 3) * 32;

    const __nv_bfloat16* gsrc[4];
    gsrc[0] = Ahi + (size_t)m0 * D_;
    gsrc[1] = Alo + (size_t)m0 * D_;
    gsrc[2] = Whi + (size_t)n0 * D_;
    gsrc[3] = Wlo + (size_t)n0 * D_;

    // --- async load of one BK=32 chunk into stage s ---
    auto issue = [&](int kt, int s) {
        uint32_t sdst = sb + s * STG_B;
        #pragma unroll
        for (int mat = 0; mat < 4; mat++) {
            const __nv_bfloat16* g = gsrc[mat] + kt * 32;
            #pragma unroll
            for (int i = 0; i < 2; i++) {
                int idx = tid + i * 256;
                int r = idx >> 2, c = idx & 3;
                cpasync16(sdst + mat*MAT_B + (uint32_t)(r*SST + c*8)*2,
                          g + (size_t)r * D_ + c * 8);
            }
        }
        CP_COMMIT();
    };

    float acc[4][4][4];
    #pragma unroll
    for (int mt = 0; mt < 4; mt++)
        #pragma unroll
        for (int nt = 0; nt < 4; nt++)
            #pragma unroll
            for (int r = 0; r < 4; r++) acc[mt][nt][r] = 0.f;

    issue(0, 0);

    const int ar   = lane & 15;
    const int ac8  = lane >> 4;
    const int brow = (lane & 7) | ((lane & 16) >> 1);
    const int bc8  = (lane >> 3) & 1;

    for (int kt = 0; kt < 32; kt++) {
        const int s = kt & 1;
        if (kt + 1 < 32) { issue(kt + 1, s ^ 1); CP_WAIT(1); }
        else             { CP_WAIT(0); }
        __syncthreads();

        const uint32_t base = sb + s * STG_B;
        #pragma unroll
        for (int k16 = 0; k16 < 2; k16++) {
            uint32_t aH[4][4], aL[4][4], bHf[2][4], bLf[2][4];
            #pragma unroll
            for (int mt = 0; mt < 4; mt++) {
                uint32_t off = (uint32_t)((wm + mt*16 + ar)*SST + k16*16 + ac8*8) * 2;
                ldmx4(aH[mt], base + 0*MAT_B + off);
                ldmx4(aL[mt], base + 1*MAT_B + off);
            }
            #pragma unroll
            for (int np = 0; np < 2; np++) {
                uint32_t off = (uint32_t)((wn + np*16 + brow)*SST + k16*16 + bc8*8) * 2;
                ldmx4(bHf[np], base + 2*MAT_B + off);
                ldmx4(bLf[np], base + 3*MAT_B + off);
            }
            #pragma unroll
            for (int mt = 0; mt < 4; mt++)
                #pragma unroll
                for (int nt = 0; nt < 4; nt++) {
                    const uint32_t* bh = &bHf[nt >> 1][(nt & 1) * 2];
                    const uint32_t* bl = &bLf[nt >> 1][(nt & 1) * 2];
                    mma16816(acc[mt][nt], aH[mt], bh);
                    mma16816(acc[mt][nt], aH[mt], bl);
                    mma16816(acc[mt][nt], aL[mt], bh);
                }
        }
        __syncthreads();
    }

    // --- epilogue ---
    const int tg = lane >> 2, tig = lane & 3;
    #pragma unroll
    for (int mt = 0; mt < 4; mt++)
        #pragma unroll
        for (int i2 = 0; i2 < 2; i2++) {
            int m = m0 + wm + mt*16 + tg + i2*8;
            #pragma unroll
            for (int nt = 0; nt < 4; nt++) {
                int n = n0 + wn + nt*8 + tig*2;
                float v0 = (acc[mt][nt][i2*2+0] + bias[n])   * scale;
                float v1 = (acc[mt][nt][i2*2+1] + bias[n+1]) * scale;
                float* dst;
                if (remap) {
                    int b = m >> 10, t = m & 1023;
                    int h = n >> 6,  d = n & 63;
                    dst = out + (((size_t)(b*H_ + h)*T_ + t))*HD + d;
                } else {
                    dst = out + (size_t)m*D_ + n;
                }
                *(float2*)dst = make_float2(v0, v1);
            }
        }
}

// ---------------------------------------------------------------------------
// Position-bias LUT: bucket depends only on rel = k - q in [-1023, 1023]
// ---------------------------------------------------------------------------
__global__ void pb_kernel(const float* __restrict__ rel_embed)
{
    int d = blockIdx.x * blockDim.x + threadIdx.x;
    if (d >= 2047) return;
    int rel = d - 1023;
    int rb  = (rel > 0) ? 160 : 0;
    int rp  = rel < 0 ? -rel : rel;
    int bucket;
    if (rp < 80) {
        bucket = rb + rp;
    } else {
        float t = logf((float)rp / 80.0f) / logf(10.0f);
        t = t * 80.0f;
        float v = 80.0f + t;
        int bi = (int)v;
        bucket = rb + (bi < 159 ? bi : 159);
    }
    #pragma unroll
    for (int h = 0; h < H_; h++)
        g_pb[h*2048 + d] = rel_embed[bucket*H_ + h];
}

// ---------------------------------------------------------------------------
// Gate
// ---------------------------------------------------------------------------
__global__ void gate_kernel(const float* __restrict__ hs,
                            const float* __restrict__ gw,
                            const float* __restrict__ gb,
                            const float* __restrict__ gc)
{
    int idx = blockIdx.x * blockDim.x + threadIdx.x;
    if (idx >= BH*T_) return;
    int t  = idx & (T_-1);
    int bh = idx >> 10;
    int h  = bh & (H_-1);
    int b  = bh >> 4;

    const float4* x = (const float4*)(hs + ((size_t)(b*T_+t))*D_ + h*HD);
    float p[8];
    #pragma unroll
    for (int e = 0; e < 8; e++) p[e] = 0.f;
    #pragma unroll
    for (int i = 0; i < 16; i++) {
        float4 xv = x[i];
        #pragma unroll
        for (int e = 0; e < 8; e++) {
            const float* w = gw + e*HD + i*4;
            p[e] += xv.x*w[0] + xv.y*w[1] + xv.z*w[2] + xv.w*w[3];
        }
    }
    float pa = p[0]+p[1]+p[2]+p[3] + gb[0]+gb[1]+gb[2]+gb[3];
    float pbv= p[4]+p[5]+p[6]+p[7] + gb[4]+gb[5]+gb[6]+gb[7];
    float ga  = 1.f/(1.f + expf(-pa));
    float gbs = 1.f/(1.f + expf(-pbv));
    g_gate[idx] = ga * (gbs * gc[h] - 1.f) + 2.f;
}

// ---------------------------------------------------------------------------
// Scores: S[bh][q][k] = Q.K + gate[bh][q] * pb[h][k-q+1023]
// ---------------------------------------------------------------------------
__global__ void scores_kernel()
{
    __shared__ float Qs[64][65];
    __shared__ float Ks[64][65];

    const int kt = blockIdx.x, qt = blockIdx.y, bh = blockIdx.z;
    const int h  = bh & 15;
    const int tid = threadIdx.x;
    const int tx = tid & 15, ty = tid >> 4;

    const float* Q = g_q + ((size_t)bh*T_ + qt*64)*HD;
    const float* K = g_k + ((size_t)bh*T_ + kt*64)*HD;

    #pragma unroll
    for (int f = tid; f < 1024; f += 256) {
        int r = f >> 4, c = (f & 15) * 4;
        float4 qv = *(const float4*)(Q + r*HD + c);
        float4 kv = *(const float4*)(K + r*HD + c);
        Qs[c+0][r]=qv.x; Qs[c+1][r]=qv.y; Qs[c+2][r]=qv.z; Qs[c+3][r]=qv.w;
        Ks[c+0][r]=kv.x; Ks[c+1][r]=kv.y; Ks[c+2][r]=kv.z; Ks[c+3][r]=kv.w;
    }
    __syncthreads();

    float acc[4][4];
    #pragma unroll
    for (int i = 0; i < 4; i++)
        #pragma unroll
        for (int j = 0; j < 4; j++) acc[i][j] = 0.f;

    #pragma unroll
    for (int d = 0; d < 64; d++) {
        float a[4], b[4];
        #pragma unroll
        for (int i = 0; i < 4; i++) a[i] = Qs[d][ty*4+i];
        #pragma unroll
        for (int j = 0; j < 4; j++) b[j] = Ks[d][tx*4+j];
        #pragma unroll
        for (int i = 0; i < 4; i++)
            #pragma unroll
            for (int j = 0; j < 4; j++) acc[i][j] += a[i]*b[j];
    }

    float gt[4];
    #pragma unroll
    for (int i = 0; i < 4; i++) gt[i] = g_gate[bh*T_ + qt*64 + ty*4 + i];

    #pragma unroll
    for (int i = 0; i < 4; i++) {
        int q = qt*64 + ty*4 + i;
        float* row = g_scores + ((size_t)bh*T_ + q)*T_;
        #pragma unroll
        for (int j = 0; j < 4; j++) {
            int k = kt*64 + tx*4 + j;
            row[k] = acc[i][j] + gt[i] * g_pb[h*2048 + (k - q + 1023)];
        }
    }
}

// ---------------------------------------------------------------------------
// Row softmax over 1024, in place
// ---------------------------------------------------------------------------
__global__ void softmax_kernel()
{
    __shared__ float smax[8], ssum[8];
    float* p = g_scores + (size_t)blockIdx.x * T_;
    int tid = threadIdx.x;

    float4 v = ((const float4*)p)[tid];
    float m = fmaxf(fmaxf(v.x, v.y), fmaxf(v.z, v.w));
    #pragma unroll
    for (int o = 16; o > 0; o >>= 1) m = fmaxf(m, __shfl_xor_sync(0xffffffffu, m, o));
    if ((tid & 31) == 0) smax[tid >> 5] = m;
    __syncthreads();
    float mt = smax[0];
    #pragma unroll
    for (int w = 1; w < 8; w++) mt = fmaxf(mt, smax[w]);

    float e0 = expf(v.x - mt), e1 = expf(v.y - mt);
    float e2 = expf(v.z - mt), e3 = expf(v.w - mt);
    float s = e0 + e1 + e2 + e3;
    #pragma unroll
    for (int o = 16; o > 0; o >>= 1) s += __shfl_xor_sync(0xffffffffu, s, o);
    if ((tid & 31) == 0) ssum[tid >> 5] = s;
    __syncthreads();
    float st = 0.f;
    #pragma unroll
    for (int w = 0; w < 8; w++) st += ssum[w];
    float inv = 1.f / st;

    float4 o4 = make_float4(e0*inv, e1*inv, e2*inv, e3*inv);
    ((float4*)p)[tid] = o4;
}

// ---------------------------------------------------------------------------
// PV
// ---------------------------------------------------------------------------
__global__ void av_kernel()
{
    __shared__ float Ps[64][68];
    __shared__ float Vs[64][68];

    const int qt = blockIdx.x, bh = blockIdx.y;
    const int b = bh >> 4, h = bh & 15;
    const int tid = threadIdx.x;
    const int tx = tid & 15, ty = tid >> 4;

    float acc[4][4];
    #pragma unroll
    for (int i = 0; i < 4; i++)
        #pragma unroll
        for (int j = 0; j < 4; j++) acc[i][j] = 0.f;

    for (int kt = 0; kt < 16; kt++) {
        const float* P = g_scores + ((size_t)bh*T_ + qt*64)*T_ + kt*64;
        const float* V = g_v + ((size_t)bh*T_ + kt*64)*HD;
        #pragma unroll
        for (int f = tid; f < 1024; f += 256) {
            int r = f >> 4, c = (f & 15) * 4;
            *(float4*)&Ps[r][c] = *(const float4*)(P + (size_t)r*T_ + c);
            *(float4*)&Vs[r][c] = *(const float4*)(V + r*HD + c);
        }
        __syncthreads();
        #pragma unroll
        for (int kk = 0; kk < 64; kk++) {
            float a[4], bb[4];
            #pragma unroll
            for (int i = 0; i < 4; i++) a[i] = Ps[ty*4+i][kk];
            #pragma unroll
            for (int j = 0; j < 4; j++) bb[j] = Vs[kk][tx*4+j];
            #pragma unroll
            for (int i = 0; i < 4; i++)
                #pragma unroll
                for (int j = 0; j < 4; j++) acc[i][j] += a[i]*bb[j];
        }
        __syncthreads();
    }

    #pragma unroll
    for (int i = 0; i < 4; i++) {
        int t = qt*64 + ty*4 + i;
        #pragma unroll
        for (int j = 0; j < 4; j++) {
            int d = tx*4 + j;
            g_ctx[((size_t)(b*T_ + t))*D_ + h*HD + d] = acc[i][j];
        }
    }
}

// ---------------------------------------------------------------------------
extern "C" void kernel_launch(void* const* d_in, const int* in_sizes, int n_in,
                              void* d_out, int out_size)
{
    const float* hs    = (const float*)d_in[0];
    const float* q_w   = (const float*)d_in[1];
    const float* q_b   = (const float*)d_in[2];
    const float* k_w   = (const float*)d_in[3];
    const float* k_b   = (const float*)d_in[4];
    const float* v_w   = (const float*)d_in[5];
    const float* v_b   = (const float*)d_in[6];
    const float* out_w = (const float*)d_in[7];
    const float* out_b = (const float*)d_in[8];
    const float* rel   = (const float*)d_in[9];
    const float* gc    = (const float*)d_in[10];
    const float* gw    = (const float*)d_in[11];
    const float* gb    = (const float*)d_in[12];

    float *pq, *pk, *pv, *pctx;
    __nv_bfloat16 *ahi, *alo, *whi, *wlo;
    cudaGetSymbolAddress((void**)&pq,  g_q);
    cudaGetSymbolAddress((void**)&pk,  g_k);
    cudaGetSymbolAddress((void**)&pv,  g_v);
    cudaGetSymbolAddress((void**)&pctx, g_ctx);
    cudaGetSymbolAddress((void**)&ahi, g_a_hi);
    cudaGetSymbolAddress((void**)&alo, g_a_lo);
    cudaGetSymbolAddress((void**)&whi, g_w_hi);
    cudaGetSymbolAddress((void**)&wlo, g_w_lo);

    cudaFuncSetAttribute(proj_mma_kernel,
                         cudaFuncAttributeMaxDynamicSharedMemorySize, SMEMT);

    pb_kernel<<<8, 256>>>(rel);
    gate_kernel<<<(BH*T_)/256, 256>>>(hs, gw, gb, gc);

    const size_t WSZ = (size_t)D_*D_;
    split_kernel<<<(M_*D_/4 + 255)/256, 256>>>(hs,  ahi, alo, M_*D_/4);
    split_kernel<<<(WSZ/4 + 255)/256, 256>>>(q_w,  whi + 0*WSZ, wlo + 0*WSZ, WSZ/4);
    split_kernel<<<(WSZ/4 + 255)/256, 256>>>(k_w,  whi + 1*WSZ, wlo + 1*WSZ, WSZ/4);
    split_kernel<<<(WSZ/4 + 255)/256, 256>>>(v_w,  whi + 2*WSZ, wlo + 2*WSZ, WSZ/4);
    split_kernel<<<(WSZ/4 + 255)/256, 256>>>(out_w, whi + 3*WSZ, wlo + 3*WSZ, WSZ/4);

    const float scaling = 0.125f;   // hd^-0.5
    dim3 pg(8, 32);
    proj_mma_kernel<<<pg, 256, SMEMT>>>(ahi, alo, whi + 0*WSZ, wlo + 0*WSZ, q_b, pq, scaling, 1);
    proj_mma_kernel<<<pg, 256, SMEMT>>>(ahi, alo, whi + 1*WSZ, wlo + 1*WSZ, k_b, pk, 1.0f, 1);
    proj_mma_kernel<<<pg, 256, SMEMT>>>(ahi, alo, whi + 2*WSZ, wlo + 2*WSZ, v_b, pv, 1.0f, 1);

    scores_kernel<<<dim3(16, 16, BH), 256>>>();
    softmax_kernel<<<BH*T_, 256>>>();
    av_kernel<<<dim3(16, BH), 256>>>();

    split_kernel<<<(M_*D_/4 + 255)/256, 256>>>(pctx, ahi, alo, M_*D_/4);
    proj_mma_kernel<<<pg, 256, SMEMT>>>(ahi, alo, whi + 3*WSZ, wlo + 3*WSZ, out_b, (float*)d_out, 1.0f, 0);
}

// round 4
// speedup vs baseline: 3.2660x; 1.8378x over previous
#include <cuda_runtime.h>
#include <cuda_bf16.h>
#include <math.h>
#include <stdint.h>

// Problem constants
#define B_  4
#define T_  1024
#define D_  1024
#define H_  16
#define HD  64
#define BH  (B_*H_)     // 64
#define M_  (B_*T_)     // 4096

// Scratch (static device globals — no allocation)
__device__ float g_gate[BH*T_];               // [bh][t]
__device__ float g_pb[H_*2048];               // [h][rel+1023]

// bf16 split buffers
__device__ __nv_bfloat16 g_a_hi[(size_t)M_*D_];   // activations hi (hs, later ctx)
__device__ __nv_bfloat16 g_a_lo[(size_t)M_*D_];
__device__ __nv_bfloat16 g_w_hi[(size_t)4*D_*D_]; // 4 weight matrices hi
__device__ __nv_bfloat16 g_w_lo[(size_t)4*D_*D_];
// q/k/v in [bh][t][d] bf16 hi/lo
__device__ __nv_bfloat16 g_qh[(size_t)BH*T_*HD];
__device__ __nv_bfloat16 g_ql[(size_t)BH*T_*HD];
__device__ __nv_bfloat16 g_kh[(size_t)BH*T_*HD];
__device__ __nv_bfloat16 g_kl[(size_t)BH*T_*HD];
__device__ __nv_bfloat16 g_vh[(size_t)BH*T_*HD];
__device__ __nv_bfloat16 g_vl[(size_t)BH*T_*HD];

// ---------------------------------------------------------------------------
// PTX helpers
// ---------------------------------------------------------------------------
__device__ __forceinline__ uint32_t smem_u32(const void* p) {
    uint32_t a;
    asm("{ .reg .u64 t; cvta.to.shared.u64 t, %1; cvt.u32.u64 %0, t; }" : "=r"(a) : "l"(p));
    return a;
}
__device__ __forceinline__ void ldmx4(uint32_t* r, uint32_t addr) {
    asm volatile("ldmatrix.sync.aligned.m8n8.x4.shared.b16 {%0,%1,%2,%3}, [%4];"
        : "=r"(r[0]), "=r"(r[1]), "=r"(r[2]), "=r"(r[3]) : "r"(addr));
}
__device__ __forceinline__ void ldmx4t(uint32_t* r, uint32_t addr) {
    asm volatile("ldmatrix.sync.aligned.m8n8.x4.trans.shared.b16 {%0,%1,%2,%3}, [%4];"
        : "=r"(r[0]), "=r"(r[1]), "=r"(r[2]), "=r"(r[3]) : "r"(addr));
}
__device__ __forceinline__ void mma16816(float* c, const uint32_t* a, const uint32_t* b) {
    asm volatile("mma.sync.aligned.m16n8k16.row.col.f32.bf16.bf16.f32 "
        "{%0,%1,%2,%3}, {%4,%5,%6,%7}, {%8,%9}, {%0,%1,%2,%3};"
        : "+f"(c[0]), "+f"(c[1]), "+f"(c[2]), "+f"(c[3])
        : "r"(a[0]), "r"(a[1]), "r"(a[2]), "r"(a[3]), "r"(b[0]), "r"(b[1]));
}
__device__ __forceinline__ void cpasync16(uint32_t dst, const void* src) {
    asm volatile("cp.async.cg.shared.global [%0], [%1], 16;" :: "r"(dst), "l"(src));
}
#define CP_COMMIT()  asm volatile("cp.async.commit_group;" ::: "memory")
#define CP_WAIT(n)   asm volatile("cp.async.wait_group %0;" :: "n"(n) : "memory")
#define SWZ(o) ((o) ^ (((o) >> 3) & 0x70))

// split pair of floats into bf16x2 hi and lo words
__device__ __forceinline__ void split2(float x, float y, uint32_t& h, uint32_t& l) {
    __nv_bfloat162 hh = __floats2bfloat162_rn(x, y);
    float hx = __low2float(hh), hy = __high2float(hh);
    __nv_bfloat162 ll = __floats2bfloat162_rn(x - hx, y - hy);
    h = *(uint32_t*)&hh;
    l = *(uint32_t*)&ll;
}

// ---------------------------------------------------------------------------
// Split fp32 -> bf16 hi/lo
// ---------------------------------------------------------------------------
__global__ void split_kernel(const float* __restrict__ x,
                             __nv_bfloat16* __restrict__ hi,
                             __nv_bfloat16* __restrict__ lo, int n4)
{
    int i = blockIdx.x * blockDim.x + threadIdx.x;
    if (i >= n4) return;
    float4 v = ((const float4*)x)[i];
    uint32_t h0, l0, h1, l1;
    split2(v.x, v.y, h0, l0);
    split2(v.z, v.w, h1, l1);
    ((uint32_t*)hi)[2*i+0] = h0; ((uint32_t*)hi)[2*i+1] = h1;
    ((uint32_t*)lo)[2*i+0] = l0; ((uint32_t*)lo)[2*i+1] = l1;
}

// ---------------------------------------------------------------------------
// mma.sync projection GEMM: C[4096,1024] = A @ W^T (bf16 hi/lo, fp32 accum)
// remap=1: write bf16 hi/lo pairs into [bh][t][d]; remap=0: fp32 row-major.
// ---------------------------------------------------------------------------
#define SST    40
#define MAT_B  (128*SST*2)
#define STG_B  (4*MAT_B)
#define SMEMT  (2*STG_B)

__global__ __launch_bounds__(256, 1)
void proj_mma_kernel(const __nv_bfloat16* __restrict__ Ahi,
                     const __nv_bfloat16* __restrict__ Alo,
                     const __nv_bfloat16* __restrict__ Whi,
                     const __nv_bfloat16* __restrict__ Wlo,
                     const float* __restrict__ bias,
                     float* __restrict__ outf,
                     __nv_bfloat16* __restrict__ outh,
                     __nv_bfloat16* __restrict__ outl,
                     float scale, int remap)
{
    extern __shared__ char sm[];
    const uint32_t sb = smem_u32(sm);
    const int tid = threadIdx.x;
    const int lane = tid & 31, wid = tid >> 5;
    const int m0 = blockIdx.y * 128, n0 = blockIdx.x * 128;
    const int wm = (wid >> 2) * 64, wn = (wid & 3) * 32;

    const __nv_bfloat16* gsrc[4];
    gsrc[0] = Ahi + (size_t)m0 * D_;
    gsrc[1] = Alo + (size_t)m0 * D_;
    gsrc[2] = Whi + (size_t)n0 * D_;
    gsrc[3] = Wlo + (size_t)n0 * D_;

    auto issue = [&](int kt, int s) {
        uint32_t sdst = sb + s * STG_B;
        #pragma unroll
        for (int mat = 0; mat < 4; mat++) {
            const __nv_bfloat16* g = gsrc[mat] + kt * 32;
            #pragma unroll
            for (int i = 0; i < 2; i++) {
                int idx = tid + i * 256;
                int r = idx >> 2, c = idx & 3;
                cpasync16(sdst + mat*MAT_B + (uint32_t)(r*SST + c*8)*2,
                          g + (size_t)r * D_ + c * 8);
            }
        }
        CP_COMMIT();
    };

    float acc[4][4][4];
    #pragma unroll
    for (int mt = 0; mt < 4; mt++)
        #pragma unroll
        for (int nt = 0; nt < 4; nt++)
            #pragma unroll
            for (int r = 0; r < 4; r++) acc[mt][nt][r] = 0.f;

    issue(0, 0);

    const int ar   = lane & 15;
    const int ac8  = lane >> 4;
    const int brow = (lane & 7) | ((lane & 16) >> 1);
    const int bc8  = (lane >> 3) & 1;

    for (int kt = 0; kt < 32; kt++) {
        const int s = kt & 1;
        if (kt + 1 < 32) { issue(kt + 1, s ^ 1); CP_WAIT(1); }
        else             { CP_WAIT(0); }
        __syncthreads();

        const uint32_t base = sb + s * STG_B;
        #pragma unroll
        for (int k16 = 0; k16 < 2; k16++) {
            uint32_t aH[4][4], aL[4][4], bHf[2][4], bLf[2][4];
            #pragma unroll
            for (int mt = 0; mt < 4; mt++) {
                uint32_t off = (uint32_t)((wm + mt*16 + ar)*SST + k16*16 + ac8*8) * 2;
                ldmx4(aH[mt], base + 0*MAT_B + off);
                ldmx4(aL[mt], base + 1*MAT_B + off);
            }
            #pragma unroll
            for (int np = 0; np < 2; np++) {
                uint32_t off = (uint32_t)((wn + np*16 + brow)*SST + k16*16 + bc8*8) * 2;
                ldmx4(bHf[np], base + 2*MAT_B + off);
                ldmx4(bLf[np], base + 3*MAT_B + off);
            }
            #pragma unroll
            for (int mt = 0; mt < 4; mt++)
                #pragma unroll
                for (int nt = 0; nt < 4; nt++) {
                    const uint32_t* bh = &bHf[nt >> 1][(nt & 1) * 2];
                    const uint32_t* bl = &bLf[nt >> 1][(nt & 1) * 2];
                    mma16816(acc[mt][nt], aH[mt], bh);
                    mma16816(acc[mt][nt], aH[mt], bl);
                    mma16816(acc[mt][nt], aL[mt], bh);
                }
        }
        __syncthreads();
    }

    const int tg = lane >> 2, tig = lane & 3;
    #pragma unroll
    for (int mt = 0; mt < 4; mt++)
        #pragma unroll
        for (int i2 = 0; i2 < 2; i2++) {
            int m = m0 + wm + mt*16 + tg + i2*8;
            #pragma unroll
            for (int nt = 0; nt < 4; nt++) {
                int n = n0 + wn + nt*8 + tig*2;
                float v0 = (acc[mt][nt][i2*2+0] + bias[n])   * scale;
                float v1 = (acc[mt][nt][i2*2+1] + bias[n+1]) * scale;
                if (remap) {
                    int b = m >> 10, t = m & 1023;
                    int h = n >> 6,  d = n & 63;
                    size_t off = (((size_t)(b*H_ + h)*T_ + t))*HD + d;
                    uint32_t hw, lw;
                    split2(v0, v1, hw, lw);
                    *(uint32_t*)(outh + off) = hw;
                    *(uint32_t*)(outl + off) = lw;
                } else {
                    *(float2*)(outf + (size_t)m*D_ + n) = make_float2(v0, v1);
                }
            }
        }
}

// ---------------------------------------------------------------------------
// Position-bias LUT
// ---------------------------------------------------------------------------
__global__ void pb_kernel(const float* __restrict__ rel_embed)
{
    int d = blockIdx.x * blockDim.x + threadIdx.x;
    if (d >= 2047) return;
    int rel = d - 1023;
    int rb  = (rel > 0) ? 160 : 0;
    int rp  = rel < 0 ? -rel : rel;
    int bucket;
    if (rp < 80) {
        bucket = rb + rp;
    } else {
        float t = logf((float)rp / 80.0f) / logf(10.0f);
        t = t * 80.0f;
        float v = 80.0f + t;
        int bi = (int)v;
        bucket = rb + (bi < 159 ? bi : 159);
    }
    #pragma unroll
    for (int h = 0; h < H_; h++)
        g_pb[h*2048 + d] = rel_embed[bucket*H_ + h];
}

// ---------------------------------------------------------------------------
// Gate
// ---------------------------------------------------------------------------
__global__ void gate_kernel(const float* __restrict__ hs,
                            const float* __restrict__ gw,
                            const float* __restrict__ gb,
                            const float* __restrict__ gc)
{
    int idx = blockIdx.x * blockDim.x + threadIdx.x;
    if (idx >= BH*T_) return;
    int t  = idx & (T_-1);
    int bh = idx >> 10;
    int h  = bh & (H_-1);
    int b  = bh >> 4;

    const float4* x = (const float4*)(hs + ((size_t)(b*T_+t))*D_ + h*HD);
    float p[8];
    #pragma unroll
    for (int e = 0; e < 8; e++) p[e] = 0.f;
    #pragma unroll
    for (int i = 0; i < 16; i++) {
        float4 xv = x[i];
        #pragma unroll
        for (int e = 0; e < 8; e++) {
            const float* w = gw + e*HD + i*4;
            p[e] += xv.x*w[0] + xv.y*w[1] + xv.z*w[2] + xv.w*w[3];
        }
    }
    float pa = p[0]+p[1]+p[2]+p[3] + gb[0]+gb[1]+gb[2]+gb[3];
    float pbv= p[4]+p[5]+p[6]+p[7] + gb[4]+gb[5]+gb[6]+gb[7];
    float ga  = 1.f/(1.f + expf(-pa));
    float gbs = 1.f/(1.f + expf(-pbv));
    g_gate[idx] = ga * (gbs * gc[h] - 1.f) + 2.f;
}

// ---------------------------------------------------------------------------
// Fused flash attention: per CTA one (bh, q-tile of 128). 8 warps, each owns
// 16 q-rows. Online softmax; QK and PV via mma.sync with bf16 hi/lo.
// Output written as bf16 hi/lo into activation buffers [b*T+t][D].
// ---------------------------------------------------------------------------
#define FTILE_B   16384                     // 128 x 64 bf16
#define F_SM_Q    0                         // Qh, Ql
#define F_SM_KV   (2*FTILE_B)               // stage s: Kh,Kl,Vh,Vl
#define F_STG_B   (4*FTILE_B)
#define F_SM_PB   (F_SM_KV + 2*F_STG_B)     // float[2][256]
#define F_SMEMT   (F_SM_PB + 2*256*4)       // 165888

__global__ __launch_bounds__(256, 1)
void flash_kernel(__nv_bfloat16* __restrict__ outh,
                  __nv_bfloat16* __restrict__ outl)
{
    extern __shared__ char sm[];
    const uint32_t sb = smem_u32(sm);
    float* pb_s = (float*)(sm + F_SM_PB);

    const int tid  = threadIdx.x;
    const int lane = tid & 31, w = tid >> 5;
    const int qt = blockIdx.x, bh = blockIdx.y;
    const int b = bh >> 4, h = bh & 15;
    const size_t bhoff = (size_t)bh * T_ * HD;

    const __nv_bfloat16* gQh = g_qh + bhoff + (size_t)qt*128*HD;
    const __nv_bfloat16* gQl = g_ql + bhoff + (size_t)qt*128*HD;

    // ---- prologue: Q + KV stage 0 + pb slice 0 ----
    #pragma unroll
    for (int i = 0; i < 4; i++) {
        int idx = tid + i * 256;
        int r = idx >> 3, c = idx & 7;
        uint32_t off = SWZ((uint32_t)(r*128 + c*16));
        cpasync16(sb + F_SM_Q + off,           gQh + r*HD + c*8);
        cpasync16(sb + F_SM_Q + FTILE_B + off, gQl + r*HD + c*8);
    }
    {
        const __nv_bfloat16* src[4] = { g_kh + bhoff, g_kl + bhoff,
                                        g_vh + bhoff, g_vl + bhoff };
        #pragma unroll
        for (int mat = 0; mat < 4; mat++)
            #pragma unroll
            for (int i = 0; i < 4; i++) {
                int idx = tid + i * 256;
                int r = idx >> 3, c = idx & 7;
                uint32_t off = SWZ((uint32_t)(r*128 + c*16));
                cpasync16(sb + F_SM_KV + mat*FTILE_B + off, src[mat] + r*HD + c*8);
            }
    }
    CP_COMMIT();
    if (tid < 255) pb_s[tid] = g_pb[h*2048 + (0 - qt)*128 + 896 + tid];
    CP_WAIT(0);
    __syncthreads();

    // ---- Q fragments (register resident) ----
    uint32_t aQh[4][4], aQl[4][4];
    {
        const int ar = lane & 15, ac8 = lane >> 4;
        #pragma unroll
        for (int k16 = 0; k16 < 4; k16++) {
            uint32_t off = SWZ((uint32_t)((w*16 + ar)*128 + k16*32 + ac8*16));
            ldmx4(aQh[k16], sb + F_SM_Q + off);
            ldmx4(aQl[k16], sb + F_SM_Q + FTILE_B + off);
        }
    }

    const int tg = lane >> 2, tig = lane & 3;
    const int qloc0 = w*16 + tg, qloc1 = qloc0 + 8;
    const float gate0 = g_gate[bh*T_ + qt*128 + qloc0];
    const float gate1 = g_gate[bh*T_ + qt*128 + qloc1];

    float m0 = -1e30f, m1 = -1e30f, l0 = 0.f, l1 = 0.f;
    float oacc[8][4];
    #pragma unroll
    for (int dt = 0; dt < 8; dt++)
        #pragma unroll
        for (int r = 0; r < 4; r++) oacc[dt][r] = 0.f;

    const int kb_row = (lane & 7) | ((lane & 16) >> 1);
    const int kb_c16 = (lane >> 3) & 1;
    const int v_row  = lane & 15;
    const int v_c16  = lane >> 4;

    for (int kt = 0; kt < 8; kt++) {
        const int s = kt & 1;
        // prefetch next KV stage + pb slice
        if (kt + 1 < 8) {
            const size_t koff = bhoff + (size_t)(kt+1)*128*HD;
            const __nv_bfloat16* src[4] = { g_kh + koff, g_kl + koff,
                                            g_vh + koff, g_vl + koff };
            uint32_t sdst = sb + F_SM_KV + (s^1)*F_STG_B;
            #pragma unroll
            for (int mat = 0; mat < 4; mat++)
                #pragma unroll
                for (int i = 0; i < 4; i++) {
                    int idx = tid + i * 256;
                    int r = idx >> 3, c = idx & 7;
                    uint32_t off = SWZ((uint32_t)(r*128 + c*16));
                    cpasync16(sdst + mat*FTILE_B + off, src[mat] + r*HD + c*8);
                }
            CP_COMMIT();
            if (tid < 255)
                pb_s[(s^1)*256 + tid] = g_pb[h*2048 + (kt+1 - qt)*128 + 896 + tid];
        }

        // ---- S = Q K^T (3-term) ----
        const uint32_t kbh = sb + F_SM_KV + s*F_STG_B;
        const uint32_t kbl = kbh + FTILE_B;
        float sacc[16][4];
        #pragma unroll
        for (int j = 0; j < 16; j++)
            #pragma unroll
            for (int r = 0; r < 4; r++) sacc[j][r] = 0.f;

        #pragma unroll
        for (int k16 = 0; k16 < 4; k16++) {
            #pragma unroll
            for (int np = 0; np < 8; np++) {
                uint32_t off = SWZ((uint32_t)((np*16 + kb_row)*128 + k16*32 + kb_c16*16));
                uint32_t bkh[4], bkl[4];
                ldmx4(bkh, kbh + off);
                ldmx4(bkl, kbl + off);
                mma16816(sacc[2*np],   aQh[k16], bkh);
                mma16816(sacc[2*np],   aQh[k16], bkl);
                mma16816(sacc[2*np],   aQl[k16], bkh);
                mma16816(sacc[2*np+1], aQh[k16], bkh+2);
                mma16816(sacc[2*np+1], aQh[k16], bkl+2);
                mma16816(sacc[2*np+1], aQl[k16], bkh+2);
            }
        }

        // ---- bias + online softmax ----
        const float* pbc = pb_s + s*256;
        float mx0 = -1e30f, mx1 = -1e30f;
        #pragma unroll
        for (int j = 0; j < 16; j++) {
            int kl0 = j*8 + 2*tig;
            sacc[j][0] += gate0 * pbc[kl0     - qloc0 + 127];
            sacc[j][1] += gate0 * pbc[kl0 + 1 - qloc0 + 127];
            sacc[j][2] += gate1 * pbc[kl0     - qloc1 + 127];
            sacc[j][3] += gate1 * pbc[kl0 + 1 - qloc1 + 127];
            mx0 = fmaxf(mx0, fmaxf(sacc[j][0], sacc[j][1]));
            mx1 = fmaxf(mx1, fmaxf(sacc[j][2], sacc[j][3]));
        }
        mx0 = fmaxf(mx0, __shfl_xor_sync(0xffffffffu, mx0, 1));
        mx0 = fmaxf(mx0, __shfl_xor_sync(0xffffffffu, mx0, 2));
        mx1 = fmaxf(mx1, __shfl_xor_sync(0xffffffffu, mx1, 1));
        mx1 = fmaxf(mx1, __shfl_xor_sync(0xffffffffu, mx1, 2));

        float nm0 = fmaxf(m0, mx0), nm1 = fmaxf(m1, mx1);
        float sc0 = __expf(m0 - nm0), sc1 = __expf(m1 - nm1);
        m0 = nm0; m1 = nm1;

        float rs0 = 0.f, rs1 = 0.f;
        #pragma unroll
        for (int j = 0; j < 16; j++) {
            sacc[j][0] = __expf(sacc[j][0] - m0);
            sacc[j][1] = __expf(sacc[j][1] - m0);
            sacc[j][2] = __expf(sacc[j][2] - m1);
            sacc[j][3] = __expf(sacc[j][3] - m1);
            rs0 += sacc[j][0] + sacc[j][1];
            rs1 += sacc[j][2] + sacc[j][3];
        }
        rs0 += __shfl_xor_sync(0xffffffffu, rs0, 1);
        rs0 += __shfl_xor_sync(0xffffffffu, rs0, 2);
        rs1 += __shfl_xor_sync(0xffffffffu, rs1, 1);
        rs1 += __shfl_xor_sync(0xffffffffu, rs1, 2);
        l0 = l0 * sc0 + rs0;
        l1 = l1 * sc1 + rs1;

        #pragma unroll
        for (int dt = 0; dt < 8; dt++) {
            oacc[dt][0] *= sc0; oacc[dt][1] *= sc0;
            oacc[dt][2] *= sc1; oacc[dt][3] *= sc1;
        }

        // ---- O += P V (3-term, P hi/lo from accumulators) ----
        const uint32_t vbh = kbh + 2*FTILE_B;
        const uint32_t vbl = vbh + FTILE_B;
        #pragma unroll
        for (int kk = 0; kk < 8; kk++) {
            uint32_t ph[4], pl[4];
            split2(sacc[2*kk][0],   sacc[2*kk][1],   ph[0], pl[0]);
            split2(sacc[2*kk][2],   sacc[2*kk][3],   ph[1], pl[1]);
            split2(sacc[2*kk+1][0], sacc[2*kk+1][1], ph[2], pl[2]);
            split2(sacc[2*kk+1][2], sacc[2*kk+1][3], ph[3], pl[3]);
            #pragma unroll
            for (int dt = 0; dt < 4; dt++) {
                uint32_t off = SWZ((uint32_t)((kk*16 + v_row)*128 + dt*32 + v_c16*16));
                uint32_t bvh[4], bvl[4];
                ldmx4t(bvh, vbh + off);
                ldmx4t(bvl, vbl + off);
                mma16816(oacc[2*dt],   ph, bvh);
                mma16816(oacc[2*dt],   ph, bvl);
                mma16816(oacc[2*dt],   pl, bvh);
                mma16816(oacc[2*dt+1], ph, bvh+2);
                mma16816(oacc[2*dt+1], ph, bvl+2);
                mma16816(oacc[2*dt+1], pl, bvh+2);
            }
        }

        if (kt + 1 < 8) {
            CP_WAIT(0);
            __syncthreads();
        }
    }

    // ---- epilogue: O /= l, write bf16 hi/lo into activation layout ----
    float il0 = 1.f / l0, il1 = 1.f / l1;
    size_t row0 = (size_t)(b*T_ + qt*128 + qloc0) * D_ + h*HD;
    size_t row1 = (size_t)(b*T_ + qt*128 + qloc1) * D_ + h*HD;
    #pragma unroll
    for (int dt = 0; dt < 8; dt++) {
        int d = dt*8 + 2*tig;
        uint32_t hw, lw;
        split2(oacc[dt][0]*il0, oacc[dt][1]*il0, hw, lw);
        *(uint32_t*)(outh + row0 + d) = hw;
        *(uint32_t*)(outl + row0 + d) = lw;
        split2(oacc[dt][2]*il1, oacc[dt][3]*il1, hw, lw);
        *(uint32_t*)(outh + row1 + d) = hw;
        *(uint32_t*)(outl + row1 + d) = lw;
    }
}

// ---------------------------------------------------------------------------
extern "C" void kernel_launch(void* const* d_in, const int* in_sizes, int n_in,
                              void* d_out, int out_size)
{
    const float* hs    = (const float*)d_in[0];
    const float* q_w   = (const float*)d_in[1];
    const float* q_b   = (const float*)d_in[2];
    const float* k_w   = (const float*)d_in[3];
    const float* k_b   = (const float*)d_in[4];
    const float* v_w   = (const float*)d_in[5];
    const float* v_b   = (const float*)d_in[6];
    const float* out_w = (const float*)d_in[7];
    const float* out_b = (const float*)d_in[8];
    const float* rel   = (const float*)d_in[9];
    const float* gc    = (const float*)d_in[10];
    const float* gw    = (const float*)d_in[11];
    const float* gb    = (const float*)d_in[12];

    __nv_bfloat16 *ahi, *alo, *whi, *wlo;
    __nv_bfloat16 *qh, *ql, *kh, *kl, *vh, *vl;
    cudaGetSymbolAddress((void**)&ahi, g_a_hi);
    cudaGetSymbolAddress((void**)&alo, g_a_lo);
    cudaGetSymbolAddress((void**)&whi, g_w_hi);
    cudaGetSymbolAddress((void**)&wlo, g_w_lo);
    cudaGetSymbolAddress((void**)&qh, g_qh);
    cudaGetSymbolAddress((void**)&ql, g_ql);
    cudaGetSymbolAddress((void**)&kh, g_kh);
    cudaGetSymbolAddress((void**)&kl, g_kl);
    cudaGetSymbolAddress((void**)&vh, g_vh);
    cudaGetSymbolAddress((void**)&vl, g_vl);

    cudaFuncSetAttribute(proj_mma_kernel,
                         cudaFuncAttributeMaxDynamicSharedMemorySize, SMEMT);
    cudaFuncSetAttribute(flash_kernel,
                         cudaFuncAttributeMaxDynamicSharedMemorySize, F_SMEMT);

    pb_kernel<<<8, 256>>>(rel);
    gate_kernel<<<(BH*T_)/256, 256>>>(hs, gw, gb, gc);

    const size_t WSZ = (size_t)D_*D_;
    split_kernel<<<(M_*D_/4 + 255)/256, 256>>>(hs,  ahi, alo, M_*D_/4);
    split_kernel<<<(WSZ/4 + 255)/256, 256>>>(q_w,  whi + 0*WSZ, wlo + 0*WSZ, WSZ/4);
    split_kernel<<<(WSZ/4 + 255)/256, 256>>>(k_w,  whi + 1*WSZ, wlo + 1*WSZ, WSZ/4);
    split_kernel<<<(WSZ/4 + 255)/256, 256>>>(v_w,  whi + 2*WSZ, wlo + 2*WSZ, WSZ/4);
    split_kernel<<<(WSZ/4 + 255)/256, 256>>>(out_w, whi + 3*WSZ, wlo + 3*WSZ, WSZ/4);

    const float scaling = 0.125f;   // hd^-0.5
    dim3 pg(8, 32);
    proj_mma_kernel<<<pg, 256, SMEMT>>>(ahi, alo, whi + 0*WSZ, wlo + 0*WSZ, q_b, nullptr, qh, ql, scaling, 1);
    proj_mma_kernel<<<pg, 256, SMEMT>>>(ahi, alo, whi + 1*WSZ, wlo + 1*WSZ, k_b, nullptr, kh, kl, 1.0f, 1);
    proj_mma_kernel<<<pg, 256, SMEMT>>>(ahi, alo, whi + 2*WSZ, wlo + 2*WSZ, v_b, nullptr, vh, vl, 1.0f, 1);

    // fused attention: writes ctx directly as split activations
    flash_kernel<<<dim3(8, BH), 256, F_SMEMT>>>(ahi, alo);

    proj_mma_kernel<<<pg, 256, SMEMT>>>(ahi, alo, whi + 3*WSZ, wlo + 3*WSZ, out_b, (float*)d_out, nullptr, nullptr, 1.0f, 0);
}

// round 6
// speedup vs baseline: 3.5338x; 1.0820x over previous
#include <cuda_runtime.h>
#include <cuda_bf16.h>
#include <math.h>
#include <stdint.h>

// Problem constants
#define B_  4
#define T_  1024
#define D_  1024
#define H_  16
#define HD  64
#define BH  (B_*H_)     // 64
#define M_  (B_*T_)     // 4096

// Scratch (static device globals — no allocation)
__device__ float g_gate[BH*T_];               // [bh][t]
__device__ float g_pb[H_*2048];               // [h][rel+1023]

// bf16 split buffers
__device__ __nv_bfloat16 g_a_hi[(size_t)M_*D_];   // activations hi (hs, later ctx)
__device__ __nv_bfloat16 g_a_lo[(size_t)M_*D_];
__device__ __nv_bfloat16 g_w_hi[(size_t)4*D_*D_]; // 4 weight matrices hi
__device__ __nv_bfloat16 g_w_lo[(size_t)4*D_*D_];
// q/k/v in [bh][t][d] bf16 hi/lo
__device__ __nv_bfloat16 g_qh[(size_t)BH*T_*HD];
__device__ __nv_bfloat16 g_ql[(size_t)BH*T_*HD];
__device__ __nv_bfloat16 g_kh[(size_t)BH*T_*HD];
__device__ __nv_bfloat16 g_kl[(size_t)BH*T_*HD];
__device__ __nv_bfloat16 g_vh[(size_t)BH*T_*HD];
__device__ __nv_bfloat16 g_vl[(size_t)BH*T_*HD];

// ---------------------------------------------------------------------------
// PTX helpers
// ---------------------------------------------------------------------------
__device__ __forceinline__ uint32_t smem_u32(const void* p) {
    uint32_t a;
    asm("{ .reg .u64 t; cvta.to.shared.u64 t, %1; cvt.u32.u64 %0, t; }" : "=r"(a) : "l"(p));
    return a;
}
__device__ __forceinline__ void ldmx4(uint32_t* r, uint32_t addr) {
    asm volatile("ldmatrix.sync.aligned.m8n8.x4.shared.b16 {%0,%1,%2,%3}, [%4];"
        : "=r"(r[0]), "=r"(r[1]), "=r"(r[2]), "=r"(r[3]) : "r"(addr));
}
__device__ __forceinline__ void ldmx4t(uint32_t* r, uint32_t addr) {
    asm volatile("ldmatrix.sync.aligned.m8n8.x4.trans.shared.b16 {%0,%1,%2,%3}, [%4];"
        : "=r"(r[0]), "=r"(r[1]), "=r"(r[2]), "=r"(r[3]) : "r"(addr));
}
__device__ __forceinline__ void mma16816(float* c, const uint32_t* a, const uint32_t* b) {
    asm volatile("mma.sync.aligned.m16n8k16.row.col.f32.bf16.bf16.f32 "
        "{%0,%1,%2,%3}, {%4,%5,%6,%7}, {%8,%9}, {%0,%1,%2,%3};"
        : "+f"(c[0]), "+f"(c[1]), "+f"(c[2]), "+f"(c[3])
        : "r"(a[0]), "r"(a[1]), "r"(a[2]), "r"(a[3]), "r"(b[0]), "r"(b[1]));
}
__device__ __forceinline__ void cpasync16(uint32_t dst, const void* src) {
    asm volatile("cp.async.cg.shared.global [%0], [%1], 16;" :: "r"(dst), "l"(src));
}
#define CP_COMMIT()  asm volatile("cp.async.commit_group;" ::: "memory")
#define CP_WAIT(n)   asm volatile("cp.async.wait_group %0;" :: "n"(n) : "memory")
#define SWZ(o) ((o) ^ (((o) >> 3) & 0x70))

// split pair of floats into bf16x2 hi and lo words
__device__ __forceinline__ void split2(float x, float y, uint32_t& h, uint32_t& l) {
    __nv_bfloat162 hh = __floats2bfloat162_rn(x, y);
    float hx = __low2float(hh), hy = __high2float(hh);
    __nv_bfloat162 ll = __floats2bfloat162_rn(x - hx, y - hy);
    h = *(uint32_t*)&hh;
    l = *(uint32_t*)&ll;
}

// ---------------------------------------------------------------------------
// Split fp32 -> bf16 hi/lo (single tensor)
// ---------------------------------------------------------------------------
__global__ void split_kernel(const float* __restrict__ x,
                             __nv_bfloat16* __restrict__ hi,
                             __nv_bfloat16* __restrict__ lo, int n4)
{
    int i = blockIdx.x * blockDim.x + threadIdx.x;
    if (i >= n4) return;
    float4 v = ((const float4*)x)[i];
    uint32_t h0, l0, h1, l1;
    split2(v.x, v.y, h0, l0);
    split2(v.z, v.w, h1, l1);
    ((uint32_t*)hi)[2*i+0] = h0; ((uint32_t*)hi)[2*i+1] = h1;
    ((uint32_t*)lo)[2*i+0] = l0; ((uint32_t*)lo)[2*i+1] = l1;
}

// Fused split of the 4 weight matrices (blockIdx.y selects matrix)
__global__ void splitw_kernel(const float* __restrict__ w0,
                              const float* __restrict__ w1,
                              const float* __restrict__ w2,
                              const float* __restrict__ w3,
                              __nv_bfloat16* __restrict__ hi,
                              __nv_bfloat16* __restrict__ lo)
{
    const int mat = blockIdx.y;
    const float* x = (mat == 0) ? w0 : (mat == 1) ? w1 : (mat == 2) ? w2 : w3;
    const size_t base = (size_t)mat * D_ * D_;
    int i = blockIdx.x * blockDim.x + threadIdx.x;     // 0 .. D*D/4
    float4 v = ((const float4*)x)[i];
    uint32_t h0, l0, h1, l1;
    split2(v.x, v.y, h0, l0);
    split2(v.z, v.w, h1, l1);
    ((uint32_t*)(hi + base))[2*i+0] = h0; ((uint32_t*)(hi + base))[2*i+1] = h1;
    ((uint32_t*)(lo + base))[2*i+0] = l0; ((uint32_t*)(lo + base))[2*i+1] = l1;
}

// ---------------------------------------------------------------------------
// mma.sync projection GEMM: C[4096,1024] = A @ W^T (bf16 hi/lo, fp32 accum)
// 2 CTAs/SM (one wave for 256 CTAs). Inner loop restructured for low regs.
// ---------------------------------------------------------------------------
#define SST    40
#define MAT_B  (128*SST*2)
#define STG_B  (4*MAT_B)
#define SMEMT  (2*STG_B)

__global__ __launch_bounds__(256, 2)
void proj_mma_kernel(const __nv_bfloat16* __restrict__ Ahi,
                     const __nv_bfloat16* __restrict__ Alo,
                     const __nv_bfloat16* __restrict__ Whi,
                     const __nv_bfloat16* __restrict__ Wlo,
                     const float* __restrict__ bias,
                     float* __restrict__ outf,
                     __nv_bfloat16* __restrict__ outh,
                     __nv_bfloat16* __restrict__ outl,
                     float scale, int remap)
{
    extern __shared__ char sm[];
    const uint32_t sb = smem_u32(sm);
    const int tid = threadIdx.x;
    const int lane = tid & 31, wid = tid >> 5;
    const int m0 = blockIdx.y * 128, n0 = blockIdx.x * 128;
    const int wm = (wid >> 2) * 64, wn = (wid & 3) * 32;

    const __nv_bfloat16* gsrc[4];
    gsrc[0] = Ahi + (size_t)m0 * D_;
    gsrc[1] = Alo + (size_t)m0 * D_;
    gsrc[2] = Whi + (size_t)n0 * D_;
    gsrc[3] = Wlo + (size_t)n0 * D_;

    auto issue = [&](int kt, int s) {
        uint32_t sdst = sb + s * STG_B;
        #pragma unroll
        for (int mat = 0; mat < 4; mat++) {
            const __nv_bfloat16* g = gsrc[mat] + kt * 32;
            #pragma unroll
            for (int i = 0; i < 2; i++) {
                int idx = tid + i * 256;
                int r = idx >> 2, c = idx & 3;
                cpasync16(sdst + mat*MAT_B + (uint32_t)(r*SST + c*8)*2,
                          g + (size_t)r * D_ + c * 8);
            }
        }
        CP_COMMIT();
    };

    float acc[4][4][4];
    #pragma unroll
    for (int mt = 0; mt < 4; mt++)
        #pragma unroll
        for (int nt = 0; nt < 4; nt++)
            #pragma unroll
            for (int r = 0; r < 4; r++) acc[mt][nt][r] = 0.f;

    issue(0, 0);

    const int ar   = lane & 15;
    const int ac8  = lane >> 4;
    const int brow = (lane & 7) | ((lane & 16) >> 1);
    const int bc8  = (lane >> 3) & 1;

    for (int kt = 0; kt < 32; kt++) {
        const int s = kt & 1;
        if (kt + 1 < 32) { issue(kt + 1, s ^ 1); CP_WAIT(1); }
        else             { CP_WAIT(0); }
        __syncthreads();

        const uint32_t base = sb + s * STG_B;
        #pragma unroll
        for (int k16 = 0; k16 < 2; k16++) {
            uint32_t aH[4][4], aL[4][4];
            #pragma unroll
            for (int mt = 0; mt < 4; mt++) {
                uint32_t off = (uint32_t)((wm + mt*16 + ar)*SST + k16*16 + ac8*8) * 2;
                ldmx4(aH[mt], base + 0*MAT_B + off);
                ldmx4(aL[mt], base + 1*MAT_B + off);
            }
            #pragma unroll
            for (int np = 0; np < 2; np++) {
                uint32_t bh4[4], bl4[4];
                uint32_t off = (uint32_t)((wn + np*16 + brow)*SST + k16*16 + bc8*8) * 2;
                ldmx4(bh4, base + 2*MAT_B + off);
                ldmx4(bl4, base + 3*MAT_B + off);
                #pragma unroll
                for (int mt = 0; mt < 4; mt++) {
                    mma16816(acc[mt][2*np],   aH[mt], bh4);
                    mma16816(acc[mt][2*np],   aH[mt], bl4);
                    mma16816(acc[mt][2*np],   aL[mt], bh4);
                    mma16816(acc[mt][2*np+1], aH[mt], bh4+2);
                    mma16816(acc[mt][2*np+1], aH[mt], bl4+2);
                    mma16816(acc[mt][2*np+1], aL[mt], bh4+2);
                }
            }
        }
        __syncthreads();
    }

    const int tg = lane >> 2, tig = lane & 3;
    #pragma unroll
    for (int mt = 0; mt < 4; mt++)
        #pragma unroll
        for (int i2 = 0; i2 < 2; i2++) {
            int m = m0 + wm + mt*16 + tg + i2*8;
            #pragma unroll
            for (int nt = 0; nt < 4; nt++) {
                int n = n0 + wn + nt*8 + tig*2;
                float v0 = (acc[mt][nt][i2*2+0] + bias[n])   * scale;
                float v1 = (acc[mt][nt][i2*2+1] + bias[n+1]) * scale;
                if (remap) {
                    int b = m >> 10, t = m & 1023;
                    int h = n >> 6,  d = n & 63;
                    size_t off = (((size_t)(b*H_ + h)*T_ + t))*HD + d;
                    uint32_t hw, lw;
                    split2(v0, v1, hw, lw);
                    *(uint32_t*)(outh + off) = hw;
                    *(uint32_t*)(outl + off) = lw;
                } else {
                    *(float2*)(outf + (size_t)m*D_ + n) = make_float2(v0, v1);
                }
            }
        }
}

// ---------------------------------------------------------------------------
// Position-bias LUT
// ---------------------------------------------------------------------------
__global__ void pb_kernel(const float* __restrict__ rel_embed)
{
    int d = blockIdx.x * blockDim.x + threadIdx.x;
    if (d >= 2047) return;
    int rel = d - 1023;
    int rb  = (rel > 0) ? 160 : 0;
    int rp  = rel < 0 ? -rel : rel;
    int bucket;
    if (rp < 80) {
        bucket = rb + rp;
    } else {
        float t = logf((float)rp / 80.0f) / logf(10.0f);
        t = t * 80.0f;
        float v = 80.0f + t;
        int bi = (int)v;
        bucket = rb + (bi < 159 ? bi : 159);
    }
    #pragma unroll
    for (int h = 0; h < H_; h++)
        g_pb[h*2048 + d] = rel_embed[bucket*H_ + h];
}

// ---------------------------------------------------------------------------
// Gate
// ---------------------------------------------------------------------------
__global__ void gate_kernel(const float* __restrict__ hs,
                            const float* __restrict__ gw,
                            const float* __restrict__ gb,
                            const float* __restrict__ gc)
{
    int idx = blockIdx.x * blockDim.x + threadIdx.x;
    if (idx >= BH*T_) return;
    int t  = idx & (T_-1);
    int bh = idx >> 10;
    int h  = bh & (H_-1);
    int b  = bh >> 4;

    const float4* x = (const float4*)(hs + ((size_t)(b*T_+t))*D_ + h*HD);
    float p[8];
    #pragma unroll
    for (int e = 0; e < 8; e++) p[e] = 0.f;
    #pragma unroll
    for (int i = 0; i < 16; i++) {
        float4 xv = x[i];
        #pragma unroll
        for (int e = 0; e < 8; e++) {
            const float* w = gw + e*HD + i*4;
            p[e] += xv.x*w[0] + xv.y*w[1] + xv.z*w[2] + xv.w*w[3];
        }
    }
    float pa = p[0]+p[1]+p[2]+p[3] + gb[0]+gb[1]+gb[2]+gb[3];
    float pbv= p[4]+p[5]+p[6]+p[7] + gb[4]+gb[5]+gb[6]+gb[7];
    float ga  = 1.f/(1.f + expf(-pa));
    float gbs = 1.f/(1.f + expf(-pbv));
    g_gate[idx] = ga * (gbs * gc[h] - 1.f) + 2.f;
}

// ---------------------------------------------------------------------------
// Fused flash attention
// ---------------------------------------------------------------------------
#define FTILE_B   16384
#define F_SM_Q    0
#define F_SM_KV   (2*FTILE_B)
#define F_STG_B   (4*FTILE_B)
#define F_SM_PB   (F_SM_KV + 2*F_STG_B)
#define F_SMEMT   (F_SM_PB + 2*256*4)

__global__ __launch_bounds__(256, 1)
void flash_kernel(__nv_bfloat16* __restrict__ outh,
                  __nv_bfloat16* __restrict__ outl)
{
    extern __shared__ char sm[];
    const uint32_t sb = smem_u32(sm);
    float* pb_s = (float*)(sm + F_SM_PB);

    const int tid  = threadIdx.x;
    const int lane = tid & 31, w = tid >> 5;
    const int qt = blockIdx.x, bh = blockIdx.y;
    const int b = bh >> 4, h = bh & 15;
    const size_t bhoff = (size_t)bh * T_ * HD;

    const __nv_bfloat16* gQh = g_qh + bhoff + (size_t)qt*128*HD;
    const __nv_bfloat16* gQl = g_ql + bhoff + (size_t)qt*128*HD;

    #pragma unroll
    for (int i = 0; i < 4; i++) {
        int idx = tid + i * 256;
        int r = idx >> 3, c = idx & 7;
        uint32_t off = SWZ((uint32_t)(r*128 + c*16));
        cpasync16(sb + F_SM_Q + off,           gQh + r*HD + c*8);
        cpasync16(sb + F_SM_Q + FTILE_B + off, gQl + r*HD + c*8);
    }
    {
        const __nv_bfloat16* src[4] = { g_kh + bhoff, g_kl + bhoff,
                                        g_vh + bhoff, g_vl + bhoff };
        #pragma unroll
        for (int mat = 0; mat < 4; mat++)
            #pragma unroll
            for (int i = 0; i < 4; i++) {
                int idx = tid + i * 256;
                int r = idx >> 3, c = idx & 7;
                uint32_t off = SWZ((uint32_t)(r*128 + c*16));
                cpasync16(sb + F_SM_KV + mat*FTILE_B + off, src[mat] + r*HD + c*8);
            }
    }
    CP_COMMIT();
    if (tid < 255) pb_s[tid] = g_pb[h*2048 + (0 - qt)*128 + 896 + tid];
    CP_WAIT(0);
    __syncthreads();

    uint32_t aQh[4][4], aQl[4][4];
    {
        const int ar = lane & 15, ac8 = lane >> 4;
        #pragma unroll
        for (int k16 = 0; k16 < 4; k16++) {
            uint32_t off = SWZ((uint32_t)((w*16 + ar)*128 + k16*32 + ac8*16));
            ldmx4(aQh[k16], sb + F_SM_Q + off);
            ldmx4(aQl[k16], sb + F_SM_Q + FTILE_B + off);
        }
    }

    const int tg = lane >> 2, tig = lane & 3;
    const int qloc0 = w*16 + tg, qloc1 = qloc0 + 8;
    const float gate0 = g_gate[bh*T_ + qt*128 + qloc0];
    const float gate1 = g_gate[bh*T_ + qt*128 + qloc1];

    float m0 = -1e30f, m1 = -1e30f, l0 = 0.f, l1 = 0.f;
    float oacc[8][4];
    #pragma unroll
    for (int dt = 0; dt < 8; dt++)
        #pragma unroll
        for (int r = 0; r < 4; r++) oacc[dt][r] = 0.f;

    const int kb_row = (lane & 7) | ((lane & 16) >> 1);
    const int kb_c16 = (lane >> 3) & 1;
    const int v_row  = lane & 15;
    const int v_c16  = lane >> 4;

    for (int kt = 0; kt < 8; kt++) {
        const int s = kt & 1;
        if (kt + 1 < 8) {
            const size_t koff = bhoff + (size_t)(kt+1)*128*HD;
            const __nv_bfloat16* src[4] = { g_kh + koff, g_kl + koff,
                                            g_vh + koff, g_vl + koff };
            uint32_t sdst = sb + F_SM_KV + (s^1)*F_STG_B;
            #pragma unroll
            for (int mat = 0; mat < 4; mat++)
                #pragma unroll
                for (int i = 0; i < 4; i++) {
                    int idx = tid + i * 256;
                    int r = idx >> 3, c = idx & 7;
                    uint32_t off = SWZ((uint32_t)(r*128 + c*16));
                    cpasync16(sdst + mat*FTILE_B + off, src[mat] + r*HD + c*8);
                }
            CP_COMMIT();
            if (tid < 255)
                pb_s[(s^1)*256 + tid] = g_pb[h*2048 + (kt+1 - qt)*128 + 896 + tid];
        }

        const uint32_t kbh = sb + F_SM_KV + s*F_STG_B;
        const uint32_t kbl = kbh + FTILE_B;
        float sacc[16][4];
        #pragma unroll
        for (int j = 0; j < 16; j++)
            #pragma unroll
            for (int r = 0; r < 4; r++) sacc[j][r] = 0.f;

        #pragma unroll
        for (int k16 = 0; k16 < 4; k16++) {
            #pragma unroll
            for (int np = 0; np < 8; np++) {
                uint32_t off = SWZ((uint32_t)((np*16 + kb_row)*128 + k16*32 + kb_c16*16));
                uint32_t bkh[4], bkl[4];
                ldmx4(bkh, kbh + off);
                ldmx4(bkl, kbl + off);
                mma16816(sacc[2*np],   aQh[k16], bkh);
                mma16816(sacc[2*np],   aQh[k16], bkl);
                mma16816(sacc[2*np],   aQl[k16], bkh);
                mma16816(sacc[2*np+1], aQh[k16], bkh+2);
                mma16816(sacc[2*np+1], aQh[k16], bkl+2);
                mma16816(sacc[2*np+1], aQl[k16], bkh+2);
            }
        }

        const float* pbc = pb_s + s*256;
        float mx0 = -1e30f, mx1 = -1e30f;
        #pragma unroll
        for (int j = 0; j < 16; j++) {
            int kl0 = j*8 + 2*tig;
            sacc[j][0] += gate0 * pbc[kl0     - qloc0 + 127];
            sacc[j][1] += gate0 * pbc[kl0 + 1 - qloc0 + 127];
            sacc[j][2] += gate1 * pbc[kl0     - qloc1 + 127];
            sacc[j][3] += gate1 * pbc[kl0 + 1 - qloc1 + 127];
            mx0 = fmaxf(mx0, fmaxf(sacc[j][0], sacc[j][1]));
            mx1 = fmaxf(mx1, fmaxf(sacc[j][2], sacc[j][3]));
        }
        mx0 = fmaxf(mx0, __shfl_xor_sync(0xffffffffu, mx0, 1));
        mx0 = fmaxf(mx0, __shfl_xor_sync(0xffffffffu, mx0, 2));
        mx1 = fmaxf(mx1, __shfl_xor_sync(0xffffffffu, mx1, 1));
        mx1 = fmaxf(mx1, __shfl_xor_sync(0xffffffffu, mx1, 2));

        float nm0 = fmaxf(m0, mx0), nm1 = fmaxf(m1, mx1);
        float sc0 = __expf(m0 - nm0), sc1 = __expf(m1 - nm1);
        m0 = nm0; m1 = nm1;

        float rs0 = 0.f, rs1 = 0.f;
        #pragma unroll
        for (int j = 0; j < 16; j++) {
            sacc[j][0] = __expf(sacc[j][0] - m0);
            sacc[j][1] = __expf(sacc[j][1] - m0);
            sacc[j][2] = __expf(sacc[j][2] - m1);
            sacc[j][3] = __expf(sacc[j][3] - m1);
            rs0 += sacc[j][0] + sacc[j][1];
            rs1 += sacc[j][2] + sacc[j][3];
        }
        rs0 += __shfl_xor_sync(0xffffffffu, rs0, 1);
        rs0 += __shfl_xor_sync(0xffffffffu, rs0, 2);
        rs1 += __shfl_xor_sync(0xffffffffu, rs1, 1);
        rs1 += __shfl_xor_sync(0xffffffffu, rs1, 2);
        l0 = l0 * sc0 + rs0;
        l1 = l1 * sc1 + rs1;

        #pragma unroll
        for (int dt = 0; dt < 8; dt++) {
            oacc[dt][0] *= sc0; oacc[dt][1] *= sc0;
            oacc[dt][2] *= sc1; oacc[dt][3] *= sc1;
        }

        const uint32_t vbh = kbh + 2*FTILE_B;
        const uint32_t vbl = vbh + FTILE_B;
        #pragma unroll
        for (int kk = 0; kk < 8; kk++) {
            uint32_t ph[4], pl[4];
            split2(sacc[2*kk][0],   sacc[2*kk][1],   ph[0], pl[0]);
            split2(sacc[2*kk][2],   sacc[2*kk][3],   ph[1], pl[1]);
            split2(sacc[2*kk+1][0], sacc[2*kk+1][1], ph[2], pl[2]);
            split2(sacc[2*kk+1][2], sacc[2*kk+1][3], ph[3], pl[3]);
            #pragma unroll
            for (int dt = 0; dt < 4; dt++) {
                uint32_t off = SWZ((uint32_t)((kk*16 + v_row)*128 + dt*32 + v_c16*16));
                uint32_t bvh[4], bvl[4];
                ldmx4t(bvh, vbh + off);
                ldmx4t(bvl, vbl + off);
                mma16816(oacc[2*dt],   ph, bvh);
                mma16816(oacc[2*dt],   ph, bvl);
                mma16816(oacc[2*dt],   pl, bvh);
                mma16816(oacc[2*dt+1], ph, bvh+2);
                mma16816(oacc[2*dt+1], ph, bvl+2);
                mma16816(oacc[2*dt+1], pl, bvh+2);
            }
        }

        if (kt + 1 < 8) {
            CP_WAIT(0);
            __syncthreads();
        }
    }

    float il0 = 1.f / l0, il1 = 1.f / l1;
    size_t row0 = (size_t)(b*T_ + qt*128 + qloc0) * D_ + h*HD;
    size_t row1 = (size_t)(b*T_ + qt*128 + qloc1) * D_ + h*HD;
    #pragma unroll
    for (int dt = 0; dt < 8; dt++) {
        int d = dt*8 + 2*tig;
        uint32_t hw, lw;
        split2(oacc[dt][0]*il0, oacc[dt][1]*il0, hw, lw);
        *(uint32_t*)(outh + row0 + d) = hw;
        *(uint32_t*)(outl + row0 + d) = lw;
        split2(oacc[dt][2]*il1, oacc[dt][3]*il1, hw, lw);
        *(uint32_t*)(outh + row1 + d) = hw;
        *(uint32_t*)(outl + row1 + d) = lw;
    }
}

// ---------------------------------------------------------------------------
extern "C" void kernel_launch(void* const* d_in, const int* in_sizes, int n_in,
                              void* d_out, int out_size)
{
    const float* hs    = (const float*)d_in[0];
    const float* q_w   = (const float*)d_in[1];
    const float* q_b   = (const float*)d_in[2];
    const float* k_w   = (const float*)d_in[3];
    const float* k_b   = (const float*)d_in[4];
    const float* v_w   = (const float*)d_in[5];
    const float* v_b   = (const float*)d_in[6];
    const float* out_w = (const float*)d_in[7];
    const float* out_b = (const float*)d_in[8];
    const float* rel   = (const float*)d_in[9];
    const float* gc    = (const float*)d_in[10];
    const float* gw    = (const float*)d_in[11];
    const float* gb    = (const float*)d_in[12];

    __nv_bfloat16 *ahi, *alo, *whi, *wlo;
    __nv_bfloat16 *qh, *ql, *kh, *kl, *vh, *vl;
    cudaGetSymbolAddress((void**)&ahi, g_a_hi);
    cudaGetSymbolAddress((void**)&alo, g_a_lo);
    cudaGetSymbolAddress((void**)&whi, g_w_hi);
    cudaGetSymbolAddress((void**)&wlo, g_w_lo);
    cudaGetSymbolAddress((void**)&qh, g_qh);
    cudaGetSymbolAddress((void**)&ql, g_ql);
    cudaGetSymbolAddress((void**)&kh, g_kh);
    cudaGetSymbolAddress((void**)&kl, g_kl);
    cudaGetSymbolAddress((void**)&vh, g_vh);
    cudaGetSymbolAddress((void**)&vl, g_vl);

    cudaFuncSetAttribute(proj_mma_kernel,
                         cudaFuncAttributeMaxDynamicSharedMemorySize, SMEMT);
    cudaFuncSetAttribute(flash_kernel,
                         cudaFuncAttributeMaxDynamicSharedMemorySize, F_SMEMT);

    pb_kernel<<<8, 256>>>(rel);
    gate_kernel<<<(BH*T_)/256, 256>>>(hs, gw, gb, gc);

    const size_t WSZ = (size_t)D_*D_;
    split_kernel<<<(M_*D_/4 + 255)/256, 256>>>(hs, ahi, alo, M_*D_/4);
    splitw_kernel<<<dim3(WSZ/4/256, 4), 256>>>(q_w, k_w, v_w, out_w, whi, wlo);

    const float scaling = 0.125f;   // hd^-0.5
    dim3 pg(8, 32);
    proj_mma_kernel<<<pg, 256, SMEMT>>>(ahi, alo, whi + 0*WSZ, wlo + 0*WSZ, q_b, nullptr, qh, ql, scaling, 1);
    proj_mma_kernel<<<pg, 256, SMEMT>>>(ahi, alo, whi + 1*WSZ, wlo + 1*WSZ, k_b, nullptr, kh, kl, 1.0f, 1);
    proj_mma_kernel<<<pg, 256, SMEMT>>>(ahi, alo, whi + 2*WSZ, wlo + 2*WSZ, v_b, nullptr, vh, vl, 1.0f, 1);

    flash_kernel<<<dim3(8, BH), 256, F_SMEMT>>>(ahi, alo);

    proj_mma_kernel<<<pg, 256, SMEMT>>>(ahi, alo, whi + 3*WSZ, wlo + 3*WSZ, out_b, (float*)d_out, nullptr, nullptr, 1.0f, 0);
}

// round 7
// speedup vs baseline: 3.6545x; 1.0342x over previous
#include <cuda_runtime.h>
#include <cuda_bf16.h>
#include <math.h>
#include <stdint.h>

// Problem constants
#define B_  4
#define T_  1024
#define D_  1024
#define H_  16
#define HD  64
#define BH  (B_*H_)     // 64
#define M_  (B_*T_)     // 4096

// Scratch (static device globals — no allocation)
__device__ float g_gate[BH*T_];               // [bh][t]
__device__ float g_pb[H_*2048];               // [h][rel+1023]

// bf16 split buffers
__device__ __nv_bfloat16 g_a_hi[(size_t)M_*D_];   // activations hi (hs, later ctx)
__device__ __nv_bfloat16 g_a_lo[(size_t)M_*D_];
__device__ __nv_bfloat16 g_w_hi[(size_t)4*D_*D_]; // 4 weight matrices hi
__device__ __nv_bfloat16 g_w_lo[(size_t)4*D_*D_];
// q/k/v in [bh][t][d] bf16 hi/lo
__device__ __nv_bfloat16 g_qh[(size_t)BH*T_*HD];
__device__ __nv_bfloat16 g_ql[(size_t)BH*T_*HD];
__device__ __nv_bfloat16 g_kh[(size_t)BH*T_*HD];
__device__ __nv_bfloat16 g_kl[(size_t)BH*T_*HD];
__device__ __nv_bfloat16 g_vh[(size_t)BH*T_*HD];
__device__ __nv_bfloat16 g_vl[(size_t)BH*T_*HD];

// ---------------------------------------------------------------------------
// PTX helpers
// ---------------------------------------------------------------------------
__device__ __forceinline__ uint32_t smem_u32(const void* p) {
    uint32_t a;
    asm("{ .reg .u64 t; cvta.to.shared.u64 t, %1; cvt.u32.u64 %0, t; }" : "=r"(a) : "l"(p));
    return a;
}
__device__ __forceinline__ void ldmx4(uint32_t* r, uint32_t addr) {
    asm volatile("ldmatrix.sync.aligned.m8n8.x4.shared.b16 {%0,%1,%2,%3}, [%4];"
        : "=r"(r[0]), "=r"(r[1]), "=r"(r[2]), "=r"(r[3]) : "r"(addr));
}
__device__ __forceinline__ void ldmx4t(uint32_t* r, uint32_t addr) {
    asm volatile("ldmatrix.sync.aligned.m8n8.x4.trans.shared.b16 {%0,%1,%2,%3}, [%4];"
        : "=r"(r[0]), "=r"(r[1]), "=r"(r[2]), "=r"(r[3]) : "r"(addr));
}
__device__ __forceinline__ void mma16816(float* c, const uint32_t* a, const uint32_t* b) {
    asm volatile("mma.sync.aligned.m16n8k16.row.col.f32.bf16.bf16.f32 "
        "{%0,%1,%2,%3}, {%4,%5,%6,%7}, {%8,%9}, {%0,%1,%2,%3};"
        : "+f"(c[0]), "+f"(c[1]), "+f"(c[2]), "+f"(c[3])
        : "r"(a[0]), "r"(a[1]), "r"(a[2]), "r"(a[3]), "r"(b[0]), "r"(b[1]));
}
__device__ __forceinline__ void cpasync16(uint32_t dst, const void* src) {
    asm volatile("cp.async.cg.shared.global [%0], [%1], 16;" :: "r"(dst), "l"(src));
}
#define CP_COMMIT()  asm volatile("cp.async.commit_group;" ::: "memory")
#define CP_WAIT(n)   asm volatile("cp.async.wait_group %0;" :: "n"(n) : "memory")
#define SWZ(o) ((o) ^ (((o) >> 3) & 0x70))

// split pair of floats into bf16x2 hi and lo words
__device__ __forceinline__ void split2(float x, float y, uint32_t& h, uint32_t& l) {
    __nv_bfloat162 hh = __floats2bfloat162_rn(x, y);
    float hx = __low2float(hh), hy = __high2float(hh);
    __nv_bfloat162 ll = __floats2bfloat162_rn(x - hx, y - hy);
    h = *(uint32_t*)&hh;
    l = *(uint32_t*)&ll;
}

// ---------------------------------------------------------------------------
// Split fp32 -> bf16 hi/lo (single tensor)
// ---------------------------------------------------------------------------
__global__ void split_kernel(const float* __restrict__ x,
                             __nv_bfloat16* __restrict__ hi,
                             __nv_bfloat16* __restrict__ lo, int n4)
{
    int i = blockIdx.x * blockDim.x + threadIdx.x;
    if (i >= n4) return;
    float4 v = ((const float4*)x)[i];
    uint32_t h0, l0, h1, l1;
    split2(v.x, v.y, h0, l0);
    split2(v.z, v.w, h1, l1);
    ((uint32_t*)hi)[2*i+0] = h0; ((uint32_t*)hi)[2*i+1] = h1;
    ((uint32_t*)lo)[2*i+0] = l0; ((uint32_t*)lo)[2*i+1] = l1;
}

// Fused split of the 4 weight matrices (blockIdx.y selects matrix)
__global__ void splitw_kernel(const float* __restrict__ w0,
                              const float* __restrict__ w1,
                              const float* __restrict__ w2,
                              const float* __restrict__ w3,
                              __nv_bfloat16* __restrict__ hi,
                              __nv_bfloat16* __restrict__ lo)
{
    const int mat = blockIdx.y;
    const float* x = (mat == 0) ? w0 : (mat == 1) ? w1 : (mat == 2) ? w2 : w3;
    const size_t base = (size_t)mat * D_ * D_;
    int i = blockIdx.x * blockDim.x + threadIdx.x;     // 0 .. D*D/4
    float4 v = ((const float4*)x)[i];
    uint32_t h0, l0, h1, l1;
    split2(v.x, v.y, h0, l0);
    split2(v.z, v.w, h1, l1);
    ((uint32_t*)(hi + base))[2*i+0] = h0; ((uint32_t*)(hi + base))[2*i+1] = h1;
    ((uint32_t*)(lo + base))[2*i+0] = l0; ((uint32_t*)(lo + base))[2*i+1] = l1;
}

// ---------------------------------------------------------------------------
// mma.sync projection GEMM core: computes one 128x128 tile of A @ W^T and
// writes either fp32 row-major or split bf16 [bh][t][d].
// ---------------------------------------------------------------------------
#define SST    40
#define MAT_B  (128*SST*2)
#define STG_B  (4*MAT_B)
#define SMEMT  (2*STG_B)

__device__ __forceinline__ void proj_tile(
    const __nv_bfloat16* __restrict__ Ahi,
    const __nv_bfloat16* __restrict__ Alo,
    const __nv_bfloat16* __restrict__ Whi,
    const __nv_bfloat16* __restrict__ Wlo,
    const float* __restrict__ bias,
    float* __restrict__ outf,
    __nv_bfloat16* __restrict__ outh,
    __nv_bfloat16* __restrict__ outl,
    float scale, int remap, int m0, int n0, char* sm)
{
    const uint32_t sb = smem_u32(sm);
    const int tid = threadIdx.x;
    const int lane = tid & 31, wid = tid >> 5;
    const int wm = (wid >> 2) * 64, wn = (wid & 3) * 32;

    const __nv_bfloat16* gsrc[4];
    gsrc[0] = Ahi + (size_t)m0 * D_;
    gsrc[1] = Alo + (size_t)m0 * D_;
    gsrc[2] = Whi + (size_t)n0 * D_;
    gsrc[3] = Wlo + (size_t)n0 * D_;

    auto issue = [&](int kt, int s) {
        uint32_t sdst = sb + s * STG_B;
        #pragma unroll
        for (int mat = 0; mat < 4; mat++) {
            const __nv_bfloat16* g = gsrc[mat] + kt * 32;
            #pragma unroll
            for (int i = 0; i < 2; i++) {
                int idx = tid + i * 256;
                int r = idx >> 2, c = idx & 3;
                cpasync16(sdst + mat*MAT_B + (uint32_t)(r*SST + c*8)*2,
                          g + (size_t)r * D_ + c * 8);
            }
        }
        CP_COMMIT();
    };

    float acc[4][4][4];
    #pragma unroll
    for (int mt = 0; mt < 4; mt++)
        #pragma unroll
        for (int nt = 0; nt < 4; nt++)
            #pragma unroll
            for (int r = 0; r < 4; r++) acc[mt][nt][r] = 0.f;

    issue(0, 0);

    const int ar   = lane & 15;
    const int ac8  = lane >> 4;
    const int brow = (lane & 7) | ((lane & 16) >> 1);
    const int bc8  = (lane >> 3) & 1;

    for (int kt = 0; kt < 32; kt++) {
        const int s = kt & 1;
        if (kt + 1 < 32) { issue(kt + 1, s ^ 1); CP_WAIT(1); }
        else             { CP_WAIT(0); }
        __syncthreads();

        const uint32_t base = sb + s * STG_B;
        #pragma unroll
        for (int k16 = 0; k16 < 2; k16++) {
            uint32_t aH[4][4], aL[4][4];
            #pragma unroll
            for (int mt = 0; mt < 4; mt++) {
                uint32_t off = (uint32_t)((wm + mt*16 + ar)*SST + k16*16 + ac8*8) * 2;
                ldmx4(aH[mt], base + 0*MAT_B + off);
                ldmx4(aL[mt], base + 1*MAT_B + off);
            }
            #pragma unroll
            for (int np = 0; np < 2; np++) {
                uint32_t bh4[4], bl4[4];
                uint32_t off = (uint32_t)((wn + np*16 + brow)*SST + k16*16 + bc8*8) * 2;
                ldmx4(bh4, base + 2*MAT_B + off);
                ldmx4(bl4, base + 3*MAT_B + off);
                #pragma unroll
                for (int mt = 0; mt < 4; mt++) {
                    mma16816(acc[mt][2*np],   aH[mt], bh4);
                    mma16816(acc[mt][2*np],   aH[mt], bl4);
                    mma16816(acc[mt][2*np],   aL[mt], bh4);
                    mma16816(acc[mt][2*np+1], aH[mt], bh4+2);
                    mma16816(acc[mt][2*np+1], aH[mt], bl4+2);
                    mma16816(acc[mt][2*np+1], aL[mt], bh4+2);
                }
            }
        }
        __syncthreads();
    }

    const int tg = lane >> 2, tig = lane & 3;
    #pragma unroll
    for (int mt = 0; mt < 4; mt++)
        #pragma unroll
        for (int i2 = 0; i2 < 2; i2++) {
            int m = m0 + wm + mt*16 + tg + i2*8;
            #pragma unroll
            for (int nt = 0; nt < 4; nt++) {
                int n = n0 + wn + nt*8 + tig*2;
                float v0 = (acc[mt][nt][i2*2+0] + bias[n])   * scale;
                float v1 = (acc[mt][nt][i2*2+1] + bias[n+1]) * scale;
                if (remap) {
                    int b = m >> 10, t = m & 1023;
                    int h = n >> 6,  d = n & 63;
                    size_t off = (((size_t)(b*H_ + h)*T_ + t))*HD + d;
                    uint32_t hw, lw;
                    split2(v0, v1, hw, lw);
                    *(uint32_t*)(outh + off) = hw;
                    *(uint32_t*)(outl + off) = lw;
                } else {
                    *(float2*)(outf + (size_t)m*D_ + n) = make_float2(v0, v1);
                }
            }
        }
}

// Merged Q/K/V projection: grid.x = 24 (mat = x>>3, n-block = x&7), grid.y = 32.
__global__ __launch_bounds__(256, 2)
void qkv_mma_kernel(const __nv_bfloat16* __restrict__ Ahi,
                    const __nv_bfloat16* __restrict__ Alo,
                    const float* __restrict__ q_b,
                    const float* __restrict__ k_b,
                    const float* __restrict__ v_b)
{
    extern __shared__ char sm[];
    const int mat = blockIdx.x >> 3;
    const int n0  = (blockIdx.x & 7) * 128;
    const int m0  = blockIdx.y * 128;
    const size_t WSZ = (size_t)D_*D_;
    const float* bias = (mat == 0) ? q_b : (mat == 1) ? k_b : v_b;
    const float scale = (mat == 0) ? 0.125f : 1.0f;
    __nv_bfloat16* outh = (mat == 0) ? g_qh : (mat == 1) ? g_kh : g_vh;
    __nv_bfloat16* outl = (mat == 0) ? g_ql : (mat == 1) ? g_kl : g_vl;

    proj_tile(Ahi, Alo, g_w_hi + mat*WSZ, g_w_lo + mat*WSZ, bias,
              nullptr, outh, outl, scale, 1, m0, n0, sm);
}

// Output projection (fp32 out)
__global__ __launch_bounds__(256, 2)
void out_mma_kernel(const __nv_bfloat16* __restrict__ Ahi,
                    const __nv_bfloat16* __restrict__ Alo,
                    const float* __restrict__ bias,
                    float* __restrict__ out)
{
    extern __shared__ char sm[];
    const size_t WSZ = (size_t)D_*D_;
    proj_tile(Ahi, Alo, g_w_hi + 3*WSZ, g_w_lo + 3*WSZ, bias,
              out, nullptr, nullptr, 1.0f, 0,
              blockIdx.y * 128, blockIdx.x * 128, sm);
}

// ---------------------------------------------------------------------------
// Position-bias LUT
// ---------------------------------------------------------------------------
__global__ void pb_kernel(const float* __restrict__ rel_embed)
{
    int d = blockIdx.x * blockDim.x + threadIdx.x;
    if (d >= 2047) return;
    int rel = d - 1023;
    int rb  = (rel > 0) ? 160 : 0;
    int rp  = rel < 0 ? -rel : rel;
    int bucket;
    if (rp < 80) {
        bucket = rb + rp;
    } else {
        float t = logf((float)rp / 80.0f) / logf(10.0f);
        t = t * 80.0f;
        float v = 80.0f + t;
        int bi = (int)v;
        bucket = rb + (bi < 159 ? bi : 159);
    }
    #pragma unroll
    for (int h = 0; h < H_; h++)
        g_pb[h*2048 + d] = rel_embed[bucket*H_ + h];
}

// ---------------------------------------------------------------------------
// Gate
// ---------------------------------------------------------------------------
__global__ void gate_kernel(const float* __restrict__ hs,
                            const float* __restrict__ gw,
                            const float* __restrict__ gb,
                            const float* __restrict__ gc)
{
    int idx = blockIdx.x * blockDim.x + threadIdx.x;
    if (idx >= BH*T_) return;
    int t  = idx & (T_-1);
    int bh = idx >> 10;
    int h  = bh & (H_-1);
    int b  = bh >> 4;

    const float4* x = (const float4*)(hs + ((size_t)(b*T_+t))*D_ + h*HD);
    float p[8];
    #pragma unroll
    for (int e = 0; e < 8; e++) p[e] = 0.f;
    #pragma unroll
    for (int i = 0; i < 16; i++) {
        float4 xv = x[i];
        #pragma unroll
        for (int e = 0; e < 8; e++) {
            const float* w = gw + e*HD + i*4;
            p[e] += xv.x*w[0] + xv.y*w[1] + xv.z*w[2] + xv.w*w[3];
        }
    }
    float pa = p[0]+p[1]+p[2]+p[3] + gb[0]+gb[1]+gb[2]+gb[3];
    float pbv= p[4]+p[5]+p[6]+p[7] + gb[4]+gb[5]+gb[6]+gb[7];
    float ga  = 1.f/(1.f + expf(-pa));
    float gbs = 1.f/(1.f + expf(-pbv));
    g_gate[idx] = ga * (gbs * gc[h] - 1.f) + 2.f;
}

// ---------------------------------------------------------------------------
// Fused flash attention
// ---------------------------------------------------------------------------
#define FTILE_B   16384
#define F_SM_Q    0
#define F_SM_KV   (2*FTILE_B)
#define F_STG_B   (4*FTILE_B)
#define F_SM_PB   (F_SM_KV + 2*F_STG_B)
#define F_SMEMT   (F_SM_PB + 2*256*4)

__global__ __launch_bounds__(256, 1)
void flash_kernel(__nv_bfloat16* __restrict__ outh,
                  __nv_bfloat16* __restrict__ outl)
{
    extern __shared__ char sm[];
    const uint32_t sb = smem_u32(sm);
    float* pb_s = (float*)(sm + F_SM_PB);

    const int tid  = threadIdx.x;
    const int lane = tid & 31, w = tid >> 5;
    const int qt = blockIdx.x, bh = blockIdx.y;
    const int b = bh >> 4, h = bh & 15;
    const size_t bhoff = (size_t)bh * T_ * HD;

    const __nv_bfloat16* gQh = g_qh + bhoff + (size_t)qt*128*HD;
    const __nv_bfloat16* gQl = g_ql + bhoff + (size_t)qt*128*HD;

    #pragma unroll
    for (int i = 0; i < 4; i++) {
        int idx = tid + i * 256;
        int r = idx >> 3, c = idx & 7;
        uint32_t off = SWZ((uint32_t)(r*128 + c*16));
        cpasync16(sb + F_SM_Q + off,           gQh + r*HD + c*8);
        cpasync16(sb + F_SM_Q + FTILE_B + off, gQl + r*HD + c*8);
    }
    {
        const __nv_bfloat16* src[4] = { g_kh + bhoff, g_kl + bhoff,
                                        g_vh + bhoff, g_vl + bhoff };
        #pragma unroll
        for (int mat = 0; mat < 4; mat++)
            #pragma unroll
            for (int i = 0; i < 4; i++) {
                int idx = tid + i * 256;
                int r = idx >> 3, c = idx & 7;
                uint32_t off = SWZ((uint32_t)(r*128 + c*16));
                cpasync16(sb + F_SM_KV + mat*FTILE_B + off, src[mat] + r*HD + c*8);
            }
    }
    CP_COMMIT();
    if (tid < 255) pb_s[tid] = g_pb[h*2048 + (0 - qt)*128 + 896 + tid];
    CP_WAIT(0);
    __syncthreads();

    uint32_t aQh[4][4], aQl[4][4];
    {
        const int ar = lane & 15, ac8 = lane >> 4;
        #pragma unroll
        for (int k16 = 0; k16 < 4; k16++) {
            uint32_t off = SWZ((uint32_t)((w*16 + ar)*128 + k16*32 + ac8*16));
            ldmx4(aQh[k16], sb + F_SM_Q + off);
            ldmx4(aQl[k16], sb + F_SM_Q + FTILE_B + off);
        }
    }

    const int tg = lane >> 2, tig = lane & 3;
    const int qloc0 = w*16 + tg, qloc1 = qloc0 + 8;
    const float gate0 = g_gate[bh*T_ + qt*128 + qloc0];
    const float gate1 = g_gate[bh*T_ + qt*128 + qloc1];

    float m0 = -1e30f, m1 = -1e30f, l0 = 0.f, l1 = 0.f;
    float oacc[8][4];
    #pragma unroll
    for (int dt = 0; dt < 8; dt++)
        #pragma unroll
        for (int r = 0; r < 4; r++) oacc[dt][r] = 0.f;

    const int kb_row = (lane & 7) | ((lane & 16) >> 1);
    const int kb_c16 = (lane >> 3) & 1;
    const int v_row  = lane & 15;
    const int v_c16  = lane >> 4;

    for (int kt = 0; kt < 8; kt++) {
        const int s = kt & 1;
        if (kt + 1 < 8) {
            const size_t koff = bhoff + (size_t)(kt+1)*128*HD;
            const __nv_bfloat16* src[4] = { g_kh + koff, g_kl + koff,
                                            g_vh + koff, g_vl + koff };
            uint32_t sdst = sb + F_SM_KV + (s^1)*F_STG_B;
            #pragma unroll
            for (int mat = 0; mat < 4; mat++)
                #pragma unroll
                for (int i = 0; i < 4; i++) {
                    int idx = tid + i * 256;
                    int r = idx >> 3, c = idx & 7;
                    uint32_t off = SWZ((uint32_t)(r*128 + c*16));
                    cpasync16(sdst + mat*FTILE_B + off, src[mat] + r*HD + c*8);
                }
            CP_COMMIT();
            if (tid < 255)
                pb_s[(s^1)*256 + tid] = g_pb[h*2048 + (kt+1 - qt)*128 + 896 + tid];
        }

        const uint32_t kbh = sb + F_SM_KV + s*F_STG_B;
        const uint32_t kbl = kbh + FTILE_B;
        float sacc[16][4];
        #pragma unroll
        for (int j = 0; j < 16; j++)
            #pragma unroll
            for (int r = 0; r < 4; r++) sacc[j][r] = 0.f;

        #pragma unroll
        for (int k16 = 0; k16 < 4; k16++) {
            #pragma unroll
            for (int np = 0; np < 8; np++) {
                uint32_t off = SWZ((uint32_t)((np*16 + kb_row)*128 + k16*32 + kb_c16*16));
                uint32_t bkh[4], bkl[4];
                ldmx4(bkh, kbh + off);
                ldmx4(bkl, kbl + off);
                mma16816(sacc[2*np],   aQh[k16], bkh);
                mma16816(sacc[2*np],   aQh[k16], bkl);
                mma16816(sacc[2*np],   aQl[k16], bkh);
                mma16816(sacc[2*np+1], aQh[k16], bkh+2);
                mma16816(sacc[2*np+1], aQh[k16], bkl+2);
                mma16816(sacc[2*np+1], aQl[k16], bkh+2);
            }
        }

        const float* pbc = pb_s + s*256;
        float mx0 = -1e30f, mx1 = -1e30f;
        #pragma unroll
        for (int j = 0; j < 16; j++) {
            int kl0 = j*8 + 2*tig;
            sacc[j][0] += gate0 * pbc[kl0     - qloc0 + 127];
            sacc[j][1] += gate0 * pbc[kl0 + 1 - qloc0 + 127];
            sacc[j][2] += gate1 * pbc[kl0     - qloc1 + 127];
            sacc[j][3] += gate1 * pbc[kl0 + 1 - qloc1 + 127];
            mx0 = fmaxf(mx0, fmaxf(sacc[j][0], sacc[j][1]));
            mx1 = fmaxf(mx1, fmaxf(sacc[j][2], sacc[j][3]));
        }
        mx0 = fmaxf(mx0, __shfl_xor_sync(0xffffffffu, mx0, 1));
        mx0 = fmaxf(mx0, __shfl_xor_sync(0xffffffffu, mx0, 2));
        mx1 = fmaxf(mx1, __shfl_xor_sync(0xffffffffu, mx1, 1));
        mx1 = fmaxf(mx1, __shfl_xor_sync(0xffffffffu, mx1, 2));

        float nm0 = fmaxf(m0, mx0), nm1 = fmaxf(m1, mx1);
        float sc0 = __expf(m0 - nm0), sc1 = __expf(m1 - nm1);
        m0 = nm0; m1 = nm1;

        float rs0 = 0.f, rs1 = 0.f;
        #pragma unroll
        for (int j = 0; j < 16; j++) {
            sacc[j][0] = __expf(sacc[j][0] - m0);
            sacc[j][1] = __expf(sacc[j][1] - m0);
            sacc[j][2] = __expf(sacc[j][2] - m1);
            sacc[j][3] = __expf(sacc[j][3] - m1);
            rs0 += sacc[j][0] + sacc[j][1];
            rs1 += sacc[j][2] + sacc[j][3];
        }
        rs0 += __shfl_xor_sync(0xffffffffu, rs0, 1);
        rs0 += __shfl_xor_sync(0xffffffffu, rs0, 2);
        rs1 += __shfl_xor_sync(0xffffffffu, rs1, 1);
        rs1 += __shfl_xor_sync(0xffffffffu, rs1, 2);
        l0 = l0 * sc0 + rs0;
        l1 = l1 * sc1 + rs1;

        #pragma unroll
        for (int dt = 0; dt < 8; dt++) {
            oacc[dt][0] *= sc0; oacc[dt][1] *= sc0;
            oacc[dt][2] *= sc1; oacc[dt][3] *= sc1;
        }

        const uint32_t vbh = kbh + 2*FTILE_B;
        const uint32_t vbl = vbh + FTILE_B;
        #pragma unroll
        for (int kk = 0; kk < 8; kk++) {
            uint32_t ph[4], pl[4];
            split2(sacc[2*kk][0],   sacc[2*kk][1],   ph[0], pl[0]);
            split2(sacc[2*kk][2],   sacc[2*kk][3],   ph[1], pl[1]);
            split2(sacc[2*kk+1][0], sacc[2*kk+1][1], ph[2], pl[2]);
            split2(sacc[2*kk+1][2], sacc[2*kk+1][3], ph[3], pl[3]);
            #pragma unroll
            for (int dt = 0; dt < 4; dt++) {
                uint32_t off = SWZ((uint32_t)((kk*16 + v_row)*128 + dt*32 + v_c16*16));
                uint32_t bvh[4], bvl[4];
                ldmx4t(bvh, vbh + off);
                ldmx4t(bvl, vbl + off);
                mma16816(oacc[2*dt],   ph, bvh);
                mma16816(oacc[2*dt],   ph, bvl);
                mma16816(oacc[2*dt],   pl, bvh);
                mma16816(oacc[2*dt+1], ph, bvh+2);
                mma16816(oacc[2*dt+1], ph, bvl+2);
                mma16816(oacc[2*dt+1], pl, bvh+2);
            }
        }

        if (kt + 1 < 8) {
            CP_WAIT(0);
            __syncthreads();
        }
    }

    float il0 = 1.f / l0, il1 = 1.f / l1;
    size_t row0 = (size_t)(b*T_ + qt*128 + qloc0) * D_ + h*HD;
    size_t row1 = (size_t)(b*T_ + qt*128 + qloc1) * D_ + h*HD;
    #pragma unroll
    for (int dt = 0; dt < 8; dt++) {
        int d = dt*8 + 2*tig;
        uint32_t hw, lw;
        split2(oacc[dt][0]*il0, oacc[dt][1]*il0, hw, lw);
        *(uint32_t*)(outh + row0 + d) = hw;
        *(uint32_t*)(outl + row0 + d) = lw;
        split2(oacc[dt][2]*il1, oacc[dt][3]*il1, hw, lw);
        *(uint32_t*)(outh + row1 + d) = hw;
        *(uint32_t*)(outl + row1 + d) = lw;
    }
}

// ---------------------------------------------------------------------------
extern "C" void kernel_launch(void* const* d_in, const int* in_sizes, int n_in,
                              void* d_out, int out_size)
{
    const float* hs    = (const float*)d_in[0];
    const float* q_w   = (const float*)d_in[1];
    const float* q_b   = (const float*)d_in[2];
    const float* k_w   = (const float*)d_in[3];
    const float* k_b   = (const float*)d_in[4];
    const float* v_w   = (const float*)d_in[5];
    const float* v_b   = (const float*)d_in[6];
    const float* out_w = (const float*)d_in[7];
    const float* out_b = (const float*)d_in[8];
    const float* rel   = (const float*)d_in[9];
    const float* gc    = (const float*)d_in[10];
    const float* gw    = (const float*)d_in[11];
    const float* gb    = (const float*)d_in[12];

    __nv_bfloat16 *ahi, *alo, *whi, *wlo;
    cudaGetSymbolAddress((void**)&ahi, g_a_hi);
    cudaGetSymbolAddress((void**)&alo, g_a_lo);
    cudaGetSymbolAddress((void**)&whi, g_w_hi);
    cudaGetSymbolAddress((void**)&wlo, g_w_lo);
    __nv_bfloat16 *fh, *fl;
    cudaGetSymbolAddress((void**)&fh, g_a_hi);
    cudaGetSymbolAddress((void**)&fl, g_a_lo);

    cudaFuncSetAttribute(qkv_mma_kernel,
                         cudaFuncAttributeMaxDynamicSharedMemorySize, SMEMT);
    cudaFuncSetAttribute(out_mma_kernel,
                         cudaFuncAttributeMaxDynamicSharedMemorySize, SMEMT);
    cudaFuncSetAttribute(flash_kernel,
                         cudaFuncAttributeMaxDynamicSharedMemorySize, F_SMEMT);

    pb_kernel<<<8, 256>>>(rel);
    gate_kernel<<<(BH*T_)/256, 256>>>(hs, gw, gb, gc);

    const size_t WSZ = (size_t)D_*D_;
    split_kernel<<<(M_*D_/4 + 255)/256, 256>>>(hs, ahi, alo, M_*D_/4);
    splitw_kernel<<<dim3(WSZ/4/256, 4), 256>>>(q_w, k_w, v_w, out_w, whi, wlo);

    // Merged Q/K/V projection: one launch, 768 CTAs
    qkv_mma_kernel<<<dim3(24, 32), 256, SMEMT>>>(ahi, alo, q_b, k_b, v_b);

    // Fused attention: writes ctx directly as split activations (reuses ahi/alo)
    flash_kernel<<<dim3(8, BH), 256, F_SMEMT>>>(fh, fl);

    out_mma_kernel<<<dim3(8, 32), 256, SMEMT>>>(ahi, alo, out_b, (float*)d_out);
}